// round 10
// baseline (speedup 1.0000x reference)
#include <cuda_runtime.h>
#include <math.h>
#include <stdint.h>

#define NB 20000
#define NA 80000
#define NE 320000
#define NC 128
#define NG 512
#define PI_F 3.14159265358979323846f

// ---------------- scratch (device globals; no allocation allowed) -------------
__device__ float g_Zb[NB * 3];
__device__ float g_cnt[NB];
__device__ float g_hs[NB * NC];            // h_s [n][c]
__device__ float g_hv[NB * 3 * NC];        // h_v [n][x][c]
__device__ float g_aggs[NB * NC];          // agg_s [n][c]
__device__ float g_aggv[NB * 3 * NC];      // agg_v [n][x][c]
__device__ float g_rfeat[NE * 16];
__device__ float g_u[NE * 3];

// ---------------- helpers ----------------------------------------------------
__device__ __forceinline__ void red_add_v4(float* addr, float4 v) {
    asm volatile("red.global.add.v4.f32 [%0], {%1,%2,%3,%4};"
                 :: "l"(addr), "f"(v.x), "f"(v.y), "f"(v.z), "f"(v.w)
                 : "memory");
}
__device__ __forceinline__ float4 f4fma(float a, float4 b, float4 c) {
    c.x += a * b.x; c.y += a * b.y; c.z += a * b.z; c.w += a * b.w; return c;
}
__device__ __forceinline__ float4 f4add(float4 a, float4 b) {
    a.x += b.x; a.y += b.y; a.z += b.z; a.w += b.w; return a;
}
__device__ __forceinline__ float4 f4scale(float4 a, float s) {
    a.x *= s; a.y *= s; a.z *= s; a.w *= s; return a;
}
__device__ __forceinline__ uint32_t f2tf32(float f) {
    uint32_t r;
    asm("cvt.rna.tf32.f32 %0, %1;" : "=r"(r) : "f"(f));
    return r;
}
__device__ __forceinline__ void mma_tf32(float& c0, float& c1, float& c2, float& c3,
                                         uint32_t a0, uint32_t a1, uint32_t a2,
                                         uint32_t a3, uint32_t b0, uint32_t b1) {
    asm volatile(
        "mma.sync.aligned.m16n8k8.row.col.f32.tf32.tf32.f32 "
        "{%0,%1,%2,%3}, {%4,%5,%6,%7}, {%8,%9}, {%0,%1,%2,%3};"
        : "+f"(c0), "+f"(c1), "+f"(c2), "+f"(c3)
        : "r"(a0), "r"(a1), "r"(a2), "r"(a3), "r"(b0), "r"(b1));
}

// ---------------- 1. atom -> block scatter (sums) -----------------------------
__global__ void atom_scatter(const float* __restrict__ H, const float* __restrict__ Z,
                             const int* __restrict__ bid, float* __restrict__ HbSum) {
    int t = blockIdx.x * blockDim.x + threadIdx.x;
    int a = t >> 5;
    if (a >= NA) return;
    int lane = t & 31;
    int b = bid[a];
    float4 v = *(const float4*)(H + (size_t)a * NC + lane * 4);
    red_add_v4(HbSum + (size_t)b * NC + lane * 4, v);
    if (lane < 3) atomicAdd(&g_Zb[b * 3 + lane], Z[a * 3 + lane]);
    if (lane == 0) atomicAdd(&g_cnt[b], 1.0f);
}

// ---------------- 2. finalize means ------------------------------------------
__global__ void finalize_blocks(float* __restrict__ Hb) {
    int t = blockIdx.x * blockDim.x + threadIdx.x;
    int b = t >> 5;
    if (b >= NB) return;
    int lane = t & 31;
    float inv = 1.0f / fmaxf(g_cnt[b], 1.0f);
    float4* p = (float4*)(Hb + (size_t)b * NC + lane * 4);
    *p = f4scale(*p, inv);
    if (lane < 3) g_Zb[b * 3 + lane] *= inv;
}

// ---------------- 3. edge geometry: u, r_feat --------------------------------
__global__ void edge_geom(const int* __restrict__ edges) {
    int e = blockIdx.x * blockDim.x + threadIdx.x;
    if (e >= NE) return;
    int s = edges[e], d_ = edges[NE + e];
    float rx = g_Zb[d_ * 3 + 0] - g_Zb[s * 3 + 0];
    float ry = g_Zb[d_ * 3 + 1] - g_Zb[s * 3 + 1];
    float rz = g_Zb[d_ * 3 + 2] - g_Zb[s * 3 + 2];
    float d = sqrtf(rx * rx + ry * ry + rz * rz + 1e-12f);
    float invd = 1.0f / d;
    g_u[e * 3 + 0] = rx * invd;
    g_u[e * 3 + 1] = ry * invd;
    g_u[e * 3 + 2] = rz * invd;
    float x = d * 0.2f;  // d / R_MAX
    float fcut = 0.0f;
    if (x < 1.0f) {
        float x2 = x * x, x4 = x2 * x2, x5 = x4 * x;
        fcut = 1.0f - 21.0f * x5 + 35.0f * x5 * x - 15.0f * x5 * x2;
    }
    float pref = 0.6324555320336759f * invd * fcut;  // sqrt(2/5) / d * fcut
    float th = PI_F * 0.2f * d;
    float s1, c1;
    sincosf(th, &s1, &c1);
    float two_c = 2.0f * c1;
    float sk = s1, skm1 = 0.0f;
    float* out = g_rfeat + (size_t)e * 16;
    #pragma unroll
    for (int k = 1; k <= 16; k++) {
        out[k - 1] = pref * sk;
        float nxt = two_c * sk - skm1;
        skm1 = sk; sk = nxt;
    }
}

// ---------------- 4. embed GEMM: h_s = Hb @ W_embed --------------------------
__global__ void __launch_bounds__(256) gemm_embed(const float* __restrict__ A,
                                                  const float* __restrict__ B) {
    extern __shared__ float sm[];
    float* Bs = sm;            // 128*128
    float* As = sm + 16384;    // 64*132
    int tid = threadIdx.x;
    for (int i = tid; i < 16384; i += 256) Bs[i] = B[i];
    int m0 = blockIdx.x * 64;
    for (int i = tid; i < 64 * 32; i += 256) {
        int r = i >> 5, kq = (i & 31) * 4;
        float4 v = make_float4(0, 0, 0, 0);
        int m = m0 + r;
        if (m < NB) v = *(const float4*)(A + (size_t)m * NC + kq);
        *(float4*)(As + r * 132 + kq) = v;
    }
    __syncthreads();
    int tr = (tid >> 4) << 2;
    int tc = (tid & 15) << 3;
    float4 acc0[4] = {}, acc1[4] = {};
    for (int k = 0; k < 128; k++) {
        float4 b0 = *(const float4*)(Bs + k * 128 + tc);
        float4 b1 = *(const float4*)(Bs + k * 128 + tc + 4);
        #pragma unroll
        for (int i = 0; i < 4; i++) {
            float a = As[(tr + i) * 132 + k];
            acc0[i] = f4fma(a, b0, acc0[i]);
            acc1[i] = f4fma(a, b1, acc1[i]);
        }
    }
    #pragma unroll
    for (int i = 0; i < 4; i++) {
        int m = m0 + tr + i;
        if (m >= NB) continue;
        *(float4*)(g_hs + (size_t)m * NC + tc) = acc0[i];
        *(float4*)(g_hs + (size_t)m * NC + tc + 4) = acc1[i];
    }
}

// ---------------- 5. edge message kernel: tf32 tensor-core MLP ----------------
// Persistent CTAs; per 64-edge tile:
//   Phase A (scalar): hidden = silu(rfeat @ Wr1 + br1)            -> hidS (tf32)
//   Phase B (mma.sync tf32): w = hidden[64,64] @ Wr2[64,256]      -> wS
//   Phase C: gather h_s/h_v, compute messages, RED scatter (as before)
// SMEM rows padded: hidS stride 72 (conflict-free A-frags), Wr2s/wS stride 264
// (conflict-free B-frags / aligned float4).
#define TILE_E 64
#define NTILES (NE / TILE_E)   // 5000
__global__ void __launch_bounds__(256) edge_msg_tc(const int* __restrict__ edges,
                                                   const float* __restrict__ Wr1,
                                                   const float* __restrict__ br1,
                                                   const float* __restrict__ Wr2) {
    extern __shared__ float sm[];
    float* Wr1s = sm;                    // 16*64     = 1024
    float* br1s = Wr1s + 1024;           // 64
    float* rfS  = br1s + 64;             // 64*17     = 1088
    float* hidS = rfS + 1088;            // 64*72     = 4608 (tf32 bits)
    float* Wr2s = hidS + 4608;           // 64*264    = 16896 (tf32 bits)
    float* wS   = Wr2s + 16896;          // 64*264    = 16896
    int tid = threadIdx.x;
    for (int i = tid; i < 1024; i += 256) Wr1s[i] = Wr1[i];
    for (int i = tid; i < 64; i += 256) br1s[i] = br1[i];
    for (int i = tid; i < 64 * 256; i += 256) {
        int h = i >> 8, c = i & 255;
        Wr2s[h * 264 + c] = __uint_as_float(f2tf32(Wr2[i]));
    }
    __syncthreads();

    int warp = tid >> 5, lane = tid & 31;
    int grp = lane >> 2, tig = lane & 3;           // mma fragment coords
    int mt = warp >> 1;                            // M-tile 0..3 (16 rows each)
    int nh = warp & 1;                             // N-half 0..1 (128 cols each)

    for (int tile = blockIdx.x; tile < NTILES; tile += gridDim.x) {
        int e0 = tile * TILE_E;
        // ---- stage rfeat tile ----
        for (int i = tid; i < TILE_E * 16; i += 256) {
            int r = i >> 4, c = i & 15;
            rfS[r * 17 + c] = g_rfeat[(size_t)(e0 + r) * 16 + c];
        }
        __syncthreads();
        // ---- Phase A: hidden (scalar), 1 thread = 1 row x 16 cols ----
        {
            int row = tid >> 2, cseg = (tid & 3) * 16;
            float acc[16];
            #pragma unroll
            for (int c = 0; c < 16; c++) acc[c] = br1s[cseg + c];
            #pragma unroll
            for (int k = 0; k < 16; k++) {
                float r = rfS[row * 17 + k];
                #pragma unroll
                for (int c = 0; c < 16; c++)
                    acc[c] += r * Wr1s[k * 64 + cseg + c];
            }
            #pragma unroll
            for (int c = 0; c < 16; c++) {
                float v = acc[c];
                v = v / (1.0f + __expf(-v));
                hidS[row * 72 + cseg + c] = __uint_as_float(f2tf32(v));
            }
        }
        __syncthreads();
        // ---- Phase B: w = hidden @ Wr2 via m16n8k8 tf32 mma ----
        {
            int m0 = mt * 16;
            // preload A fragments for all 8 k-steps
            uint32_t af[8][4];
            const float* h0p = hidS + (size_t)(m0 + grp) * 72;
            const float* h8p = h0p + 8 * 72;
            #pragma unroll
            for (int kk = 0; kk < 8; kk++) {
                int kb = kk * 8 + tig;
                af[kk][0] = __float_as_uint(h0p[kb]);
                af[kk][1] = __float_as_uint(h8p[kb]);
                af[kk][2] = __float_as_uint(h0p[kb + 4]);
                af[kk][3] = __float_as_uint(h8p[kb + 4]);
            }
            #pragma unroll 4
            for (int nt = 0; nt < 16; nt++) {
                int n0 = nh * 128 + nt * 8;
                float c0 = 0, c1 = 0, c2 = 0, c3 = 0;
                #pragma unroll
                for (int kk = 0; kk < 8; kk++) {
                    const float* bp = Wr2s + (size_t)(kk * 8 + tig) * 264 + n0 + grp;
                    uint32_t b0 = __float_as_uint(bp[0]);
                    uint32_t b1 = __float_as_uint(bp[4 * 264]);
                    mma_tf32(c0, c1, c2, c3, af[kk][0], af[kk][1], af[kk][2],
                             af[kk][3], b0, b1);
                }
                float* wp0 = wS + (size_t)(m0 + grp) * 264 + n0 + 2 * tig;
                wp0[0] = c0; wp0[1] = c1;
                wp0[8 * 264] = c2; wp0[8 * 264 + 1] = c3;
            }
        }
        __syncthreads();
        // ---- Phase C: gather + messages + scatter (8 edges per warp) ----
        {
            int c0i = lane * 4;
            #pragma unroll
            for (int j = 0; j < 8; j++) {
                int r = warp * 8 + j;
                int e = e0 + r;
                int s = edges[e], dst = edges[NE + e];
                if (s == dst) continue;  // mask==0
                float4 ws = *(const float4*)(wS + (size_t)r * 264 + c0i);
                float4 wv = *(const float4*)(wS + (size_t)r * 264 + 128 + c0i);
                float4 hs = *(const float4*)(g_hs + (size_t)s * NC + c0i);
                float4 ms = make_float4(ws.x * hs.x, ws.y * hs.y,
                                        ws.z * hs.z, ws.w * hs.w);
                red_add_v4(g_aggs + (size_t)dst * NC + c0i, ms);
                float u0 = g_u[e * 3 + 0], u1 = g_u[e * 3 + 1], u2 = g_u[e * 3 + 2];
                const float* hvp = g_hv + (size_t)s * 384;
                float* avp = g_aggv + (size_t)dst * 384;
                float u3[3] = {u0, u1, u2};
                #pragma unroll
                for (int x = 0; x < 3; x++) {
                    float4 hv4 = *(const float4*)(hvp + x * NC + c0i);
                    float u = u3[x];
                    float4 mv;
                    mv.x = wv.x * (hv4.x + hs.x * u);
                    mv.y = wv.y * (hv4.y + hs.y * u);
                    mv.z = wv.z * (hv4.z + hs.z * u);
                    mv.w = wv.w * (hv4.w + hs.w * u);
                    red_add_v4(avp + x * NC + c0i, mv);
                }
            }
        }
        __syncthreads();
    }
}

// ---------------- 6. node s-update GEMM --------------------------------------
__global__ void __launch_bounds__(256) gemm_s(const float* __restrict__ Wsl, int l,
                                              float* __restrict__ outB) {
    extern __shared__ float sm[];
    float* W0 = sm;
    float* W1 = sm + 16384;
    float* As = sm + 32768;  // 64*132
    const float* W2 = Wsl + 32768;
    int tid = threadIdx.x;
    for (int i = tid; i < 2 * 16384; i += 256) sm[i] = Wsl[i];
    int m0 = blockIdx.x * 64;
    for (int i = tid; i < 64 * 32; i += 256) {
        int r = i >> 5, kq = (i & 31) * 4;
        float4 v = make_float4(0, 0, 0, 0);
        int m = m0 + r;
        if (m < NB) v = *(const float4*)(g_aggs + (size_t)m * NC + kq);
        *(float4*)(As + r * 132 + kq) = v;
    }
    __syncthreads();
    int tr = (tid >> 4) << 2;
    int tc = (tid & 15) << 3;
    float4 acc0[4] = {}, acc1[4] = {};
    for (int k = 0; k < 128; k++) {
        float4 b00 = *(const float4*)(W0 + k * 128 + tc);
        float4 b01 = *(const float4*)(W0 + k * 128 + tc + 4);
        float4 b10 = *(const float4*)(W1 + k * 128 + tc);
        float4 b11 = *(const float4*)(W1 + k * 128 + tc + 4);
        float4 b20 = __ldg((const float4*)(W2 + k * 128 + tc));
        float4 b21 = __ldg((const float4*)(W2 + k * 128 + tc + 4));
        #pragma unroll
        for (int i = 0; i < 4; i++) {
            float a = As[(tr + i) * 132 + k];
            float a2 = a * a, a3 = a2 * a;
            acc0[i] = f4fma(a, b00, acc0[i]);
            acc0[i] = f4fma(a2, b10, acc0[i]);
            acc0[i] = f4fma(a3, b20, acc0[i]);
            acc1[i] = f4fma(a, b01, acc1[i]);
            acc1[i] = f4fma(a2, b11, acc1[i]);
            acc1[i] = f4fma(a3, b21, acc1[i]);
        }
    }
    #pragma unroll
    for (int i = 0; i < 4; i++) {
        int m = m0 + tr + i;
        if (m >= NB) continue;
        float* hsrow = g_hs + (size_t)m * NC + tc;
        float4 v0 = acc0[i], v1 = acc1[i];
        if (l) {
            v0 = f4add(v0, *(float4*)hsrow);
            v1 = f4add(v1, *(float4*)(hsrow + 4));
        }
        *(float4*)hsrow = v0;
        *(float4*)(hsrow + 4) = v1;
        float* fo = outB + (size_t)m * 1024 + l * 512 + tc;
        *(float4*)fo = v0;
        *(float4*)(fo + 4) = v1;
    }
}

// ---------------- 7. node v-update GEMM --------------------------------------
__global__ void __launch_bounds__(256) gemm_v(const float* __restrict__ Wvl,
                                              const float* __restrict__ wsvl, int l,
                                              float* __restrict__ outB) {
    extern __shared__ float sm[];
    float* Bs = sm;            // 128*128
    float* As = sm + 16384;    // 64*132
    __shared__ float wsvs[128];
    int tid = threadIdx.x;
    for (int i = tid; i < 16384; i += 256) Bs[i] = Wvl[i];
    if (tid < 128) wsvs[tid] = wsvl[tid];
    int m0 = blockIdx.x * 64;
    for (int i = tid; i < 64 * 32; i += 256) {
        int r = i >> 5, kq = (i & 31) * 4;
        float4 v = make_float4(0, 0, 0, 0);
        int m = m0 + r;
        if (m < NB * 3) v = *(const float4*)(g_aggv + (size_t)m * NC + kq);
        *(float4*)(As + r * 132 + kq) = v;
    }
    __syncthreads();
    int tr = (tid >> 4) << 2;
    int tc = (tid & 15) << 3;
    float4 acc0[4] = {}, acc1[4] = {};
    for (int k = 0; k < 128; k++) {
        float4 b0 = *(const float4*)(Bs + k * 128 + tc);
        float4 b1 = *(const float4*)(Bs + k * 128 + tc + 4);
        #pragma unroll
        for (int i = 0; i < 4; i++) {
            float a = As[(tr + i) * 132 + k];
            acc0[i] = f4fma(a, b0, acc0[i]);
            acc1[i] = f4fma(a, b1, acc1[i]);
        }
    }
    #pragma unroll
    for (int i = 0; i < 4; i++) {
        int m = m0 + tr + i;
        if (m >= NB * 3) continue;
        int n = m / 3;
        int x = m - 3 * n;
        float4 av0 = *(float4*)(As + (tr + i) * 132 + tc);
        float4 av1 = *(float4*)(As + (tr + i) * 132 + tc + 4);
        float4 as0 = *(const float4*)(g_aggs + (size_t)n * NC + tc);
        float4 as1 = *(const float4*)(g_aggs + (size_t)n * NC + tc + 4);
        float4 sv0 = *(const float4*)(wsvs + tc);
        float4 sv1 = *(const float4*)(wsvs + tc + 4);
        float4 r0 = acc0[i], r1 = acc1[i];
        r0.x += sv0.x * as0.x * av0.x; r0.y += sv0.y * as0.y * av0.y;
        r0.z += sv0.z * as0.z * av0.z; r0.w += sv0.w * as0.w * av0.w;
        r1.x += sv1.x * as1.x * av1.x; r1.y += sv1.y * as1.y * av1.y;
        r1.z += sv1.z * as1.z * av1.z; r1.w += sv1.w * as1.w * av1.w;
        float* hvrow = g_hv + (size_t)m * NC + tc;
        if (l) {
            r0 = f4add(r0, *(float4*)hvrow);
            r1 = f4add(r1, *(float4*)(hvrow + 4));
        }
        *(float4*)hvrow = r0;
        *(float4*)(hvrow + 4) = r1;
        // feats layout: 128 + c*3 + x
        float* fo = outB + (size_t)n * 1024 + l * 512 + 128 + x;
        fo[(tc + 0) * 3] = r0.x; fo[(tc + 1) * 3] = r0.y;
        fo[(tc + 2) * 3] = r0.z; fo[(tc + 3) * 3] = r0.w;
        fo[(tc + 4) * 3] = r1.x; fo[(tc + 5) * 3] = r1.y;
        fo[(tc + 6) * 3] = r1.z; fo[(tc + 7) * 3] = r1.w;
    }
}

// ---------------- 8. normalize rows + scatter to graphs ----------------------
__global__ void norm_block(float* __restrict__ outB, float* __restrict__ outC,
                           const int* __restrict__ batch_id) {
    int t = blockIdx.x * blockDim.x + threadIdx.x;
    int n = t >> 5;
    if (n >= NB) return;
    int lane = t & 31;
    float* row = outB + (size_t)n * 1024;
    float4 v[8];
    float ss = 0.0f;
    #pragma unroll
    for (int i = 0; i < 8; i++) {
        v[i] = *(float4*)(row + i * 128 + lane * 4);
        ss += v[i].x * v[i].x + v[i].y * v[i].y + v[i].z * v[i].z + v[i].w * v[i].w;
    }
    #pragma unroll
    for (int o = 16; o; o >>= 1) ss += __shfl_xor_sync(0xffffffffu, ss, o);
    float inv = 1.0f / fmaxf(sqrtf(ss), 1e-12f);
    int b = batch_id[n];
    float* grow = outC + (size_t)b * 1024;
    #pragma unroll
    for (int i = 0; i < 8; i++) {
        v[i] = f4scale(v[i], inv);
        *(float4*)(row + i * 128 + lane * 4) = v[i];
        red_add_v4(grow + i * 128 + lane * 4, v[i]);
    }
}

__global__ void norm_g(float* __restrict__ outC) {
    int t = blockIdx.x * blockDim.x + threadIdx.x;
    int n = t >> 5;
    if (n >= NG) return;
    int lane = t & 31;
    float* row = outC + (size_t)n * 1024;
    float4 v[8];
    float ss = 0.0f;
    #pragma unroll
    for (int i = 0; i < 8; i++) {
        v[i] = *(float4*)(row + i * 128 + lane * 4);
        ss += v[i].x * v[i].x + v[i].y * v[i].y + v[i].z * v[i].z + v[i].w * v[i].w;
    }
    #pragma unroll
    for (int o = 16; o; o >>= 1) ss += __shfl_xor_sync(0xffffffffu, ss, o);
    float inv = 1.0f / fmaxf(sqrtf(ss), 1e-12f);
    #pragma unroll
    for (int i = 0; i < 8; i++)
        *(float4*)(row + i * 128 + lane * 4) = f4scale(v[i], inv);
}

// ---------------- launch ------------------------------------------------------
extern "C" void kernel_launch(void* const* d_in, const int* in_sizes, int n_in,
                              void* d_out, int out_size) {
    const float* H       = (const float*)d_in[0];
    const float* Z       = (const float*)d_in[1];
    const float* W_embed = (const float*)d_in[2];
    const float* Wr1     = (const float*)d_in[3];
    const float* br1     = (const float*)d_in[4];
    const float* Wr2     = (const float*)d_in[5];
    const float* Ws      = (const float*)d_in[6];
    const float* Wv      = (const float*)d_in[7];
    const float* wsv     = (const float*)d_in[8];
    const int* block_id  = (const int*)d_in[9];
    const int* batch_id  = (const int*)d_in[10];
    const int* edges     = (const int*)d_in[11];

    float* outA = (float*)d_out;                    // Hb        [20000,128]
    float* outB = outA + (size_t)NB * NC;           // block_repr[20000,1024]
    float* outC = outB + (size_t)NB * 1024;         // graph_repr[512,1024]

    const int EM_SMEM = (1024 + 64 + 1088 + 4608 + 16896 + 16896) * 4;  // 162304
    const int GS_SMEM = (2 * 16384 + 64 * 132) * 4;                 // 164864
    const int GV_SMEM = (16384 + 64 * 132) * 4;                     // 99328

    cudaFuncSetAttribute(edge_msg_tc, cudaFuncAttributeMaxDynamicSharedMemorySize, EM_SMEM);
    cudaFuncSetAttribute(gemm_s,      cudaFuncAttributeMaxDynamicSharedMemorySize, GS_SMEM);
    cudaFuncSetAttribute(gemm_v,      cudaFuncAttributeMaxDynamicSharedMemorySize, GV_SMEM);
    cudaFuncSetAttribute(gemm_embed,  cudaFuncAttributeMaxDynamicSharedMemorySize, GV_SMEM);

    void *pZb, *pcnt, *phv, *paggs, *paggv;
    cudaGetSymbolAddress(&pZb, g_Zb);
    cudaGetSymbolAddress(&pcnt, g_cnt);
    cudaGetSymbolAddress(&phv, g_hv);
    cudaGetSymbolAddress(&paggs, g_aggs);
    cudaGetSymbolAddress(&paggv, g_aggv);

    cudaMemsetAsync(outA, 0, (size_t)NB * NC * 4);
    cudaMemsetAsync(outC, 0, (size_t)NG * 1024 * 4);
    cudaMemsetAsync(pZb, 0, (size_t)NB * 3 * 4);
    cudaMemsetAsync(pcnt, 0, (size_t)NB * 4);
    cudaMemsetAsync(phv, 0, (size_t)NB * 384 * 4);

    atom_scatter<<<(NA * 32 + 255) / 256, 256>>>(H, Z, block_id, outA);
    finalize_blocks<<<(NB * 32 + 255) / 256, 256>>>(outA);
    gemm_embed<<<(NB + 63) / 64, 256, GV_SMEM>>>(outA, W_embed);
    edge_geom<<<(NE + 255) / 256, 256>>>(edges);

    for (int l = 0; l < 2; l++) {
        cudaMemsetAsync(paggs, 0, (size_t)NB * NC * 4);
        cudaMemsetAsync(paggv, 0, (size_t)NB * 384 * 4);
        edge_msg_tc<<<148, 256, EM_SMEM>>>(edges, Wr1 + l * 16 * 64, br1 + l * 64,
                                           Wr2 + l * 64 * 256);
        gemm_s<<<(NB + 63) / 64, 256, GS_SMEM>>>(Ws + (size_t)l * 3 * 16384, l, outB);
        gemm_v<<<(NB * 3 + 63) / 64, 256, GV_SMEM>>>(Wv + (size_t)l * 16384,
                                                     wsv + l * 128, l, outB);
    }

    norm_block<<<(NB * 32 + 255) / 256, 256>>>(outB, outC, batch_id);
    norm_g<<<(NG * 32 + 255) / 256, 256>>>(outC);
}

// round 11
// speedup vs baseline: 1.6541x; 1.6541x over previous
#include <cuda_runtime.h>
#include <math.h>
#include <stdint.h>

#define NB 20000
#define NA 80000
#define NE 320000
#define NC 128
#define NG 512
#define TBINS 16384
#define PI_F 3.14159265358979323846f

// ---------------- scratch (device globals; no allocation allowed) -------------
__device__ float g_Zb[NB * 3];
__device__ float g_cnt[NB];
__device__ float g_hs[NB * NC];            // h_s [n][c]
__device__ float g_hv[NB * 3 * NC];        // h_v [n][x][c]
__device__ float g_aggs[NB * NC];          // agg_s [n][c]
__device__ float g_aggv[NB * 3 * NC];      // agg_v [n][x][c]
__device__ float g_d[NE];
__device__ float g_u[NE * 3];
__device__ float g_wtab[(TBINS + 1) * 256];  // w(d) table rows: [ws(128) | wv(128)]

// ---------------- helpers ----------------------------------------------------
__device__ __forceinline__ void red_add_v4(float* addr, float4 v) {
    asm volatile("red.global.add.v4.f32 [%0], {%1,%2,%3,%4};"
                 :: "l"(addr), "f"(v.x), "f"(v.y), "f"(v.z), "f"(v.w)
                 : "memory");
}
__device__ __forceinline__ float4 f4fma(float a, float4 b, float4 c) {
    c.x += a * b.x; c.y += a * b.y; c.z += a * b.z; c.w += a * b.w; return c;
}
__device__ __forceinline__ float4 f4add(float4 a, float4 b) {
    a.x += b.x; a.y += b.y; a.z += b.z; a.w += b.w; return a;
}
__device__ __forceinline__ float4 f4scale(float4 a, float s) {
    a.x *= s; a.y *= s; a.z *= s; a.w *= s; return a;
}
__device__ __forceinline__ float4 f4lerp(float4 a, float4 b, float f) {
    a.x += f * (b.x - a.x); a.y += f * (b.y - a.y);
    a.z += f * (b.z - a.z); a.w += f * (b.w - a.w); return a;
}

// ---------------- 1. atom -> block scatter (sums) -----------------------------
__global__ void atom_scatter(const float* __restrict__ H, const float* __restrict__ Z,
                             const int* __restrict__ bid, float* __restrict__ HbSum) {
    int t = blockIdx.x * blockDim.x + threadIdx.x;
    int a = t >> 5;
    if (a >= NA) return;
    int lane = t & 31;
    int b = bid[a];
    float4 v = *(const float4*)(H + (size_t)a * NC + lane * 4);
    red_add_v4(HbSum + (size_t)b * NC + lane * 4, v);
    if (lane < 3) atomicAdd(&g_Zb[b * 3 + lane], Z[a * 3 + lane]);
    if (lane == 0) atomicAdd(&g_cnt[b], 1.0f);
}

// ---------------- 2. finalize means ------------------------------------------
__global__ void finalize_blocks(float* __restrict__ Hb) {
    int t = blockIdx.x * blockDim.x + threadIdx.x;
    int b = t >> 5;
    if (b >= NB) return;
    int lane = t & 31;
    float inv = 1.0f / fmaxf(g_cnt[b], 1.0f);
    float4* p = (float4*)(Hb + (size_t)b * NC + lane * 4);
    *p = f4scale(*p, inv);
    if (lane < 3) g_Zb[b * 3 + lane] *= inv;
}

// ---------------- 3. edge geometry: d, u --------------------------------------
__global__ void edge_geom(const int* __restrict__ edges) {
    int e = blockIdx.x * blockDim.x + threadIdx.x;
    if (e >= NE) return;
    int s = edges[e], d_ = edges[NE + e];
    float rx = g_Zb[d_ * 3 + 0] - g_Zb[s * 3 + 0];
    float ry = g_Zb[d_ * 3 + 1] - g_Zb[s * 3 + 1];
    float rz = g_Zb[d_ * 3 + 2] - g_Zb[s * 3 + 2];
    float d = sqrtf(rx * rx + ry * ry + rz * rz + 1e-12f);
    float invd = 1.0f / d;
    g_d[e] = d;
    g_u[e * 3 + 0] = rx * invd;
    g_u[e * 3 + 1] = ry * invd;
    g_u[e * 3 + 2] = rz * invd;
}

// ---------------- 4. embed GEMM: h_s = Hb @ W_embed --------------------------
__global__ void __launch_bounds__(256) gemm_embed(const float* __restrict__ A,
                                                  const float* __restrict__ B) {
    extern __shared__ float sm[];
    float* Bs = sm;            // 128*128
    float* As = sm + 16384;    // 64*132
    int tid = threadIdx.x;
    for (int i = tid; i < 16384; i += 256) Bs[i] = B[i];
    int m0 = blockIdx.x * 64;
    for (int i = tid; i < 64 * 32; i += 256) {
        int r = i >> 5, kq = (i & 31) * 4;
        float4 v = make_float4(0, 0, 0, 0);
        int m = m0 + r;
        if (m < NB) v = *(const float4*)(A + (size_t)m * NC + kq);
        *(float4*)(As + r * 132 + kq) = v;
    }
    __syncthreads();
    int tr = (tid >> 4) << 2;
    int tc = (tid & 15) << 3;
    float4 acc0[4] = {}, acc1[4] = {};
    for (int k = 0; k < 128; k++) {
        float4 b0 = *(const float4*)(Bs + k * 128 + tc);
        float4 b1 = *(const float4*)(Bs + k * 128 + tc + 4);
        #pragma unroll
        for (int i = 0; i < 4; i++) {
            float a = As[(tr + i) * 132 + k];
            acc0[i] = f4fma(a, b0, acc0[i]);
            acc1[i] = f4fma(a, b1, acc1[i]);
        }
    }
    #pragma unroll
    for (int i = 0; i < 4; i++) {
        int m = m0 + tr + i;
        if (m >= NB) continue;
        *(float4*)(g_hs + (size_t)m * NC + tc) = acc0[i];
        *(float4*)(g_hs + (size_t)m * NC + tc + 4) = acc1[i];
    }
}

// ---------------- 5a. build w(d) table: one warp per grid row -----------------
// w is a function of d alone: tabulate ws|wv over d in [0,5], TBINS+1 rows.
__global__ void __launch_bounds__(256) build_wtab(const float* __restrict__ Wr1,
                                                  const float* __restrict__ br1,
                                                  const float* __restrict__ Wr2) {
    extern __shared__ float sm[];
    float* Wr1s = sm;                 // 16*64
    float* br1s = Wr1s + 1024;        // 64
    float* Wr2s = br1s + 64;          // 64*256
    float* hids = Wr2s + 16384;       // 8*64
    int tid = threadIdx.x;
    for (int i = tid; i < 1024; i += 256) Wr1s[i] = Wr1[i];
    for (int i = tid; i < 64; i += 256) br1s[i] = br1[i];
    for (int i = tid; i < 16384; i += 256) Wr2s[i] = Wr2[i];
    __syncthreads();

    int warp = tid >> 5, lane = tid & 31;
    float* hid = hids + warp * 64;
    int row = blockIdx.x * 8 + warp;
    if (row > TBINS) return;
    float d = fmaxf(row * (5.0f / TBINS), 1e-6f);

    // r_feat(d) for k = lane+1 (lanes 0..15)
    float rv = 0.0f;
    if (lane < 16) {
        float x = d * 0.2f;
        float fcut = 0.0f;
        if (x < 1.0f) {
            float x2 = x * x, x5 = x2 * x2 * x;
            fcut = 1.0f - 21.0f * x5 + 35.0f * x5 * x - 15.0f * x5 * x2;
        }
        float pref = 0.6324555320336759f / d * fcut;
        rv = pref * sinf((lane + 1) * (PI_F * 0.2f) * d);
    }
    // hidden = silu(r_feat @ Wr1 + br1)
    float h0 = br1s[lane], h1 = br1s[lane + 32];
    #pragma unroll
    for (int k = 0; k < 16; k++) {
        float r = __shfl_sync(0xffffffffu, rv, k);
        h0 += r * Wr1s[k * 64 + lane];
        h1 += r * Wr1s[k * 64 + lane + 32];
    }
    h0 = h0 / (1.0f + __expf(-h0));
    h1 = h1 / (1.0f + __expf(-h1));
    __syncwarp();
    hid[lane] = h0;
    hid[lane + 32] = h1;
    __syncwarp();
    // w = hidden @ Wr2
    int c0 = lane * 4;
    float4 ws = make_float4(0, 0, 0, 0), wv = make_float4(0, 0, 0, 0);
    #pragma unroll 8
    for (int h = 0; h < 64; h++) {
        float hv = hid[h];
        ws = f4fma(hv, *(const float4*)(Wr2s + h * 256 + c0), ws);
        wv = f4fma(hv, *(const float4*)(Wr2s + h * 256 + 128 + c0), wv);
    }
    *(float4*)(g_wtab + (size_t)row * 256 + c0) = ws;
    *(float4*)(g_wtab + (size_t)row * 256 + 128 + c0) = wv;
}

// ---------------- 5b. edge apply: table lerp + gather + scatter ---------------
// One warp per edge (grid-stride). No SMEM, no MLP — pure L2-bound.
__global__ void __launch_bounds__(256) edge_apply(const int* __restrict__ edges) {
    int t = blockIdx.x * blockDim.x + threadIdx.x;
    int gw = t >> 5, lane = t & 31;
    int stride = (gridDim.x * blockDim.x) >> 5;
    int c0 = lane * 4;
    for (int e = gw; e < NE; e += stride) {
        int s = edges[e], dst = edges[NE + e];
        if (s == dst) continue;  // mask==0
        float d = g_d[e];
        float tt = fminf(d, 5.0f) * (TBINS / 5.0f);
        int idx = min((int)tt, TBINS - 1);
        float f = tt - (float)idx;
        const float* r0 = g_wtab + (size_t)idx * 256;
        float4 ws = f4lerp(*(const float4*)(r0 + c0),
                           *(const float4*)(r0 + 256 + c0), f);
        float4 wv = f4lerp(*(const float4*)(r0 + 128 + c0),
                           *(const float4*)(r0 + 384 + c0), f);
        float4 hs = *(const float4*)(g_hs + (size_t)s * NC + c0);
        float4 ms = make_float4(ws.x * hs.x, ws.y * hs.y, ws.z * hs.z, ws.w * hs.w);
        red_add_v4(g_aggs + (size_t)dst * NC + c0, ms);
        float u0 = g_u[e * 3 + 0], u1 = g_u[e * 3 + 1], u2 = g_u[e * 3 + 2];
        const float* hvp = g_hv + (size_t)s * 384;
        float* avp = g_aggv + (size_t)dst * 384;
        float u3[3] = {u0, u1, u2};
        #pragma unroll
        for (int x = 0; x < 3; x++) {
            float4 hv4 = *(const float4*)(hvp + x * NC + c0);
            float u = u3[x];
            float4 mv;
            mv.x = wv.x * (hv4.x + hs.x * u);
            mv.y = wv.y * (hv4.y + hs.y * u);
            mv.z = wv.z * (hv4.z + hs.z * u);
            mv.w = wv.w * (hv4.w + hs.w * u);
            red_add_v4(avp + x * NC + c0, mv);
        }
    }
}

// ---------------- 6. node s-update GEMM --------------------------------------
__global__ void __launch_bounds__(256) gemm_s(const float* __restrict__ Wsl, int l,
                                              float* __restrict__ outB) {
    extern __shared__ float sm[];
    float* W0 = sm;
    float* W1 = sm + 16384;
    float* As = sm + 32768;  // 64*132
    const float* W2 = Wsl + 32768;
    int tid = threadIdx.x;
    for (int i = tid; i < 2 * 16384; i += 256) sm[i] = Wsl[i];
    int m0 = blockIdx.x * 64;
    for (int i = tid; i < 64 * 32; i += 256) {
        int r = i >> 5, kq = (i & 31) * 4;
        float4 v = make_float4(0, 0, 0, 0);
        int m = m0 + r;
        if (m < NB) v = *(const float4*)(g_aggs + (size_t)m * NC + kq);
        *(float4*)(As + r * 132 + kq) = v;
    }
    __syncthreads();
    int tr = (tid >> 4) << 2;
    int tc = (tid & 15) << 3;
    float4 acc0[4] = {}, acc1[4] = {};
    for (int k = 0; k < 128; k++) {
        float4 b00 = *(const float4*)(W0 + k * 128 + tc);
        float4 b01 = *(const float4*)(W0 + k * 128 + tc + 4);
        float4 b10 = *(const float4*)(W1 + k * 128 + tc);
        float4 b11 = *(const float4*)(W1 + k * 128 + tc + 4);
        float4 b20 = __ldg((const float4*)(W2 + k * 128 + tc));
        float4 b21 = __ldg((const float4*)(W2 + k * 128 + tc + 4));
        #pragma unroll
        for (int i = 0; i < 4; i++) {
            float a = As[(tr + i) * 132 + k];
            float a2 = a * a, a3 = a2 * a;
            acc0[i] = f4fma(a, b00, acc0[i]);
            acc0[i] = f4fma(a2, b10, acc0[i]);
            acc0[i] = f4fma(a3, b20, acc0[i]);
            acc1[i] = f4fma(a, b01, acc1[i]);
            acc1[i] = f4fma(a2, b11, acc1[i]);
            acc1[i] = f4fma(a3, b21, acc1[i]);
        }
    }
    #pragma unroll
    for (int i = 0; i < 4; i++) {
        int m = m0 + tr + i;
        if (m >= NB) continue;
        float* hsrow = g_hs + (size_t)m * NC + tc;
        float4 v0 = acc0[i], v1 = acc1[i];
        if (l) {
            v0 = f4add(v0, *(float4*)hsrow);
            v1 = f4add(v1, *(float4*)(hsrow + 4));
        }
        *(float4*)hsrow = v0;
        *(float4*)(hsrow + 4) = v1;
        float* fo = outB + (size_t)m * 1024 + l * 512 + tc;
        *(float4*)fo = v0;
        *(float4*)(fo + 4) = v1;
    }
}

// ---------------- 7. node v-update GEMM --------------------------------------
__global__ void __launch_bounds__(256) gemm_v(const float* __restrict__ Wvl,
                                              const float* __restrict__ wsvl, int l,
                                              float* __restrict__ outB) {
    extern __shared__ float sm[];
    float* Bs = sm;            // 128*128
    float* As = sm + 16384;    // 64*132
    __shared__ float wsvs[128];
    int tid = threadIdx.x;
    for (int i = tid; i < 16384; i += 256) Bs[i] = Wvl[i];
    if (tid < 128) wsvs[tid] = wsvl[tid];
    int m0 = blockIdx.x * 64;
    for (int i = tid; i < 64 * 32; i += 256) {
        int r = i >> 5, kq = (i & 31) * 4;
        float4 v = make_float4(0, 0, 0, 0);
        int m = m0 + r;
        if (m < NB * 3) v = *(const float4*)(g_aggv + (size_t)m * NC + kq);
        *(float4*)(As + r * 132 + kq) = v;
    }
    __syncthreads();
    int tr = (tid >> 4) << 2;
    int tc = (tid & 15) << 3;
    float4 acc0[4] = {}, acc1[4] = {};
    for (int k = 0; k < 128; k++) {
        float4 b0 = *(const float4*)(Bs + k * 128 + tc);
        float4 b1 = *(const float4*)(Bs + k * 128 + tc + 4);
        #pragma unroll
        for (int i = 0; i < 4; i++) {
            float a = As[(tr + i) * 132 + k];
            acc0[i] = f4fma(a, b0, acc0[i]);
            acc1[i] = f4fma(a, b1, acc1[i]);
        }
    }
    #pragma unroll
    for (int i = 0; i < 4; i++) {
        int m = m0 + tr + i;
        if (m >= NB * 3) continue;
        int n = m / 3;
        int x = m - 3 * n;
        float4 av0 = *(float4*)(As + (tr + i) * 132 + tc);
        float4 av1 = *(float4*)(As + (tr + i) * 132 + tc + 4);
        float4 as0 = *(const float4*)(g_aggs + (size_t)n * NC + tc);
        float4 as1 = *(const float4*)(g_aggs + (size_t)n * NC + tc + 4);
        float4 sv0 = *(const float4*)(wsvs + tc);
        float4 sv1 = *(const float4*)(wsvs + tc + 4);
        float4 r0 = acc0[i], r1 = acc1[i];
        r0.x += sv0.x * as0.x * av0.x; r0.y += sv0.y * as0.y * av0.y;
        r0.z += sv0.z * as0.z * av0.z; r0.w += sv0.w * as0.w * av0.w;
        r1.x += sv1.x * as1.x * av1.x; r1.y += sv1.y * as1.y * av1.y;
        r1.z += sv1.z * as1.z * av1.z; r1.w += sv1.w * as1.w * av1.w;
        float* hvrow = g_hv + (size_t)m * NC + tc;
        if (l) {
            r0 = f4add(r0, *(float4*)hvrow);
            r1 = f4add(r1, *(float4*)(hvrow + 4));
        }
        *(float4*)hvrow = r0;
        *(float4*)(hvrow + 4) = r1;
        // feats layout: 128 + c*3 + x
        float* fo = outB + (size_t)n * 1024 + l * 512 + 128 + x;
        fo[(tc + 0) * 3] = r0.x; fo[(tc + 1) * 3] = r0.y;
        fo[(tc + 2) * 3] = r0.z; fo[(tc + 3) * 3] = r0.w;
        fo[(tc + 4) * 3] = r1.x; fo[(tc + 5) * 3] = r1.y;
        fo[(tc + 6) * 3] = r1.z; fo[(tc + 7) * 3] = r1.w;
    }
}

// ---------------- 8. normalize rows + scatter to graphs ----------------------
__global__ void norm_block(float* __restrict__ outB, float* __restrict__ outC,
                           const int* __restrict__ batch_id) {
    int t = blockIdx.x * blockDim.x + threadIdx.x;
    int n = t >> 5;
    if (n >= NB) return;
    int lane = t & 31;
    float* row = outB + (size_t)n * 1024;
    float4 v[8];
    float ss = 0.0f;
    #pragma unroll
    for (int i = 0; i < 8; i++) {
        v[i] = *(float4*)(row + i * 128 + lane * 4);
        ss += v[i].x * v[i].x + v[i].y * v[i].y + v[i].z * v[i].z + v[i].w * v[i].w;
    }
    #pragma unroll
    for (int o = 16; o; o >>= 1) ss += __shfl_xor_sync(0xffffffffu, ss, o);
    float inv = 1.0f / fmaxf(sqrtf(ss), 1e-12f);
    int b = batch_id[n];
    float* grow = outC + (size_t)b * 1024;
    #pragma unroll
    for (int i = 0; i < 8; i++) {
        v[i] = f4scale(v[i], inv);
        *(float4*)(row + i * 128 + lane * 4) = v[i];
        red_add_v4(grow + i * 128 + lane * 4, v[i]);
    }
}

__global__ void norm_g(float* __restrict__ outC) {
    int t = blockIdx.x * blockDim.x + threadIdx.x;
    int n = t >> 5;
    if (n >= NG) return;
    int lane = t & 31;
    float* row = outC + (size_t)n * 1024;
    float4 v[8];
    float ss = 0.0f;
    #pragma unroll
    for (int i = 0; i < 8; i++) {
        v[i] = *(float4*)(row + i * 128 + lane * 4);
        ss += v[i].x * v[i].x + v[i].y * v[i].y + v[i].z * v[i].z + v[i].w * v[i].w;
    }
    #pragma unroll
    for (int o = 16; o; o >>= 1) ss += __shfl_xor_sync(0xffffffffu, ss, o);
    float inv = 1.0f / fmaxf(sqrtf(ss), 1e-12f);
    #pragma unroll
    for (int i = 0; i < 8; i++)
        *(float4*)(row + i * 128 + lane * 4) = f4scale(v[i], inv);
}

// ---------------- launch ------------------------------------------------------
extern "C" void kernel_launch(void* const* d_in, const int* in_sizes, int n_in,
                              void* d_out, int out_size) {
    const float* H       = (const float*)d_in[0];
    const float* Z       = (const float*)d_in[1];
    const float* W_embed = (const float*)d_in[2];
    const float* Wr1     = (const float*)d_in[3];
    const float* br1     = (const float*)d_in[4];
    const float* Wr2     = (const float*)d_in[5];
    const float* Ws      = (const float*)d_in[6];
    const float* Wv      = (const float*)d_in[7];
    const float* wsv     = (const float*)d_in[8];
    const int* block_id  = (const int*)d_in[9];
    const int* batch_id  = (const int*)d_in[10];
    const int* edges     = (const int*)d_in[11];

    float* outA = (float*)d_out;                    // Hb        [20000,128]
    float* outB = outA + (size_t)NB * NC;           // block_repr[20000,1024]
    float* outC = outB + (size_t)NB * 1024;         // graph_repr[512,1024]

    const int BT_SMEM = (1024 + 64 + 16384 + 8 * 64) * 4;           // 71936
    const int GS_SMEM = (2 * 16384 + 64 * 132) * 4;                 // 164864
    const int GV_SMEM = (16384 + 64 * 132) * 4;                     // 99328

    cudaFuncSetAttribute(build_wtab, cudaFuncAttributeMaxDynamicSharedMemorySize, BT_SMEM);
    cudaFuncSetAttribute(gemm_s,     cudaFuncAttributeMaxDynamicSharedMemorySize, GS_SMEM);
    cudaFuncSetAttribute(gemm_v,     cudaFuncAttributeMaxDynamicSharedMemorySize, GV_SMEM);
    cudaFuncSetAttribute(gemm_embed, cudaFuncAttributeMaxDynamicSharedMemorySize, GV_SMEM);

    void *pZb, *pcnt, *phv, *paggs, *paggv;
    cudaGetSymbolAddress(&pZb, g_Zb);
    cudaGetSymbolAddress(&pcnt, g_cnt);
    cudaGetSymbolAddress(&phv, g_hv);
    cudaGetSymbolAddress(&paggs, g_aggs);
    cudaGetSymbolAddress(&paggv, g_aggv);

    cudaMemsetAsync(outA, 0, (size_t)NB * NC * 4);
    cudaMemsetAsync(outC, 0, (size_t)NG * 1024 * 4);
    cudaMemsetAsync(pZb, 0, (size_t)NB * 3 * 4);
    cudaMemsetAsync(pcnt, 0, (size_t)NB * 4);
    cudaMemsetAsync(phv, 0, (size_t)NB * 384 * 4);

    atom_scatter<<<(NA * 32 + 255) / 256, 256>>>(H, Z, block_id, outA);
    finalize_blocks<<<(NB * 32 + 255) / 256, 256>>>(outA);
    gemm_embed<<<(NB + 63) / 64, 256, GV_SMEM>>>(outA, W_embed);
    edge_geom<<<(NE + 255) / 256, 256>>>(edges);

    for (int l = 0; l < 2; l++) {
        cudaMemsetAsync(paggs, 0, (size_t)NB * NC * 4);
        cudaMemsetAsync(paggv, 0, (size_t)NB * 384 * 4);
        build_wtab<<<(TBINS + 1 + 7) / 8, 256, BT_SMEM>>>(Wr1 + l * 16 * 64,
                                                          br1 + l * 64,
                                                          Wr2 + l * 64 * 256);
        edge_apply<<<2048, 256>>>(edges);
        gemm_s<<<(NB + 63) / 64, 256, GS_SMEM>>>(Ws + (size_t)l * 3 * 16384, l, outB);
        gemm_v<<<(NB * 3 + 63) / 64, 256, GV_SMEM>>>(Wv + (size_t)l * 16384,
                                                     wsv + l * 128, l, outB);
    }

    norm_block<<<(NB * 32 + 255) / 256, 256>>>(outB, outC, batch_id);
    norm_g<<<(NG * 32 + 255) / 256, 256>>>(outC);
}

// round 12
// speedup vs baseline: 1.7321x; 1.0471x over previous
#include <cuda_runtime.h>
#include <math.h>
#include <stdint.h>

#define NB 20000
#define NA 80000
#define NE 320000
#define NC 128
#define NG 512
#define TBINS 16384
#define PI_F 3.14159265358979323846f

// ---------------- scratch (device globals; no allocation allowed) -------------
__device__ float g_Zb[NB * 3];
__device__ float g_cnt[NB];
__device__ float g_hs[NB * NC];            // h_s [n][c]
__device__ float g_hv[NB * 3 * NC];        // h_v [n][x][c]
__device__ float g_aggs[NB * NC];          // agg_s [n][c]
__device__ float g_aggv[NB * 3 * NC];      // agg_v [n][x][c]
__device__ float g_d[NE];
__device__ float g_u[NE * 3];
__device__ float g_wtab[(TBINS + 1) * 256]; // w(d) rows: [ws(128) | wv(128)]
__device__ int   g_deg[NB];
__device__ int   g_off[NB + 1];
__device__ int   g_cur[NB];
__device__ int   g_perm[NE];

// ---------------- helpers ----------------------------------------------------
__device__ __forceinline__ void red_add_v4(float* addr, float4 v) {
    asm volatile("red.global.add.v4.f32 [%0], {%1,%2,%3,%4};"
                 :: "l"(addr), "f"(v.x), "f"(v.y), "f"(v.z), "f"(v.w)
                 : "memory");
}
__device__ __forceinline__ float4 f4fma(float a, float4 b, float4 c) {
    c.x += a * b.x; c.y += a * b.y; c.z += a * b.z; c.w += a * b.w; return c;
}
__device__ __forceinline__ float4 f4add(float4 a, float4 b) {
    a.x += b.x; a.y += b.y; a.z += b.z; a.w += b.w; return a;
}
__device__ __forceinline__ float4 f4scale(float4 a, float s) {
    a.x *= s; a.y *= s; a.z *= s; a.w *= s; return a;
}
__device__ __forceinline__ float4 f4lerp(float4 a, float4 b, float f) {
    a.x += f * (b.x - a.x); a.y += f * (b.y - a.y);
    a.z += f * (b.z - a.z); a.w += f * (b.w - a.w); return a;
}

// ---------------- 1. atom -> block scatter (sums) -----------------------------
__global__ void atom_scatter(const float* __restrict__ H, const float* __restrict__ Z,
                             const int* __restrict__ bid, float* __restrict__ HbSum) {
    int t = blockIdx.x * blockDim.x + threadIdx.x;
    int a = t >> 5;
    if (a >= NA) return;
    int lane = t & 31;
    int b = bid[a];
    float4 v = *(const float4*)(H + (size_t)a * NC + lane * 4);
    red_add_v4(HbSum + (size_t)b * NC + lane * 4, v);
    if (lane < 3) atomicAdd(&g_Zb[b * 3 + lane], Z[a * 3 + lane]);
    if (lane == 0) atomicAdd(&g_cnt[b], 1.0f);
}

// ---------------- 2. finalize means ------------------------------------------
__global__ void finalize_blocks(float* __restrict__ Hb) {
    int t = blockIdx.x * blockDim.x + threadIdx.x;
    int b = t >> 5;
    if (b >= NB) return;
    int lane = t & 31;
    float inv = 1.0f / fmaxf(g_cnt[b], 1.0f);
    float4* p = (float4*)(Hb + (size_t)b * NC + lane * 4);
    *p = f4scale(*p, inv);
    if (lane < 3) g_Zb[b * 3 + lane] *= inv;
}

// ---------------- 3. edge geometry: d, u + degree histogram -------------------
__global__ void edge_geom(const int* __restrict__ edges) {
    int e = blockIdx.x * blockDim.x + threadIdx.x;
    if (e >= NE) return;
    int s = edges[e], d_ = edges[NE + e];
    float rx = g_Zb[d_ * 3 + 0] - g_Zb[s * 3 + 0];
    float ry = g_Zb[d_ * 3 + 1] - g_Zb[s * 3 + 1];
    float rz = g_Zb[d_ * 3 + 2] - g_Zb[s * 3 + 2];
    float d = sqrtf(rx * rx + ry * ry + rz * rz + 1e-12f);
    float invd = 1.0f / d;
    g_d[e] = d;
    g_u[e * 3 + 0] = rx * invd;
    g_u[e * 3 + 1] = ry * invd;
    g_u[e * 3 + 2] = rz * invd;
    if (s != d_) atomicAdd(&g_deg[d_], 1);   // masked edges never enter lists
}

// ---------------- 3b. exclusive scan of degrees (single CTA) ------------------
__global__ void scan_offsets() {
    __shared__ int partial[256];
    const int CH = (NB + 255) / 256;  // 79
    int t = threadIdx.x;
    int base = t * CH;
    int sum = 0;
    for (int i = 0; i < CH; i++) {
        int idx = base + i;
        if (idx < NB) sum += g_deg[idx];
    }
    partial[t] = sum;
    __syncthreads();
    for (int off = 1; off < 256; off <<= 1) {
        int v = 0;
        if (t >= off) v = partial[t - off];
        __syncthreads();
        if (t >= off) partial[t] += v;
        __syncthreads();
    }
    int run = (t == 0) ? 0 : partial[t - 1];
    for (int i = 0; i < CH; i++) {
        int idx = base + i;
        if (idx < NB) {
            g_off[idx] = run;
            g_cur[idx] = run;
            run += g_deg[idx];
        }
    }
    if (t == 255) g_off[NB] = run;
}

// ---------------- 3c. scatter edges into dst-sorted order ---------------------
__global__ void scatter_perm(const int* __restrict__ edges) {
    int e = blockIdx.x * blockDim.x + threadIdx.x;
    if (e >= NE) return;
    int s = edges[e], dst = edges[NE + e];
    if (s == dst) return;
    int pos = atomicAdd(&g_cur[dst], 1);
    g_perm[pos] = e;
}

// ---------------- 4. embed GEMM: h_s = Hb @ W_embed --------------------------
__global__ void __launch_bounds__(256) gemm_embed(const float* __restrict__ A,
                                                  const float* __restrict__ B) {
    extern __shared__ float sm[];
    float* Bs = sm;            // 128*128
    float* As = sm + 16384;    // 64*132
    int tid = threadIdx.x;
    for (int i = tid; i < 16384; i += 256) Bs[i] = B[i];
    int m0 = blockIdx.x * 64;
    for (int i = tid; i < 64 * 32; i += 256) {
        int r = i >> 5, kq = (i & 31) * 4;
        float4 v = make_float4(0, 0, 0, 0);
        int m = m0 + r;
        if (m < NB) v = *(const float4*)(A + (size_t)m * NC + kq);
        *(float4*)(As + r * 132 + kq) = v;
    }
    __syncthreads();
    int tr = (tid >> 4) << 2;
    int tc = (tid & 15) << 3;
    float4 acc0[4] = {}, acc1[4] = {};
    for (int k = 0; k < 128; k++) {
        float4 b0 = *(const float4*)(Bs + k * 128 + tc);
        float4 b1 = *(const float4*)(Bs + k * 128 + tc + 4);
        #pragma unroll
        for (int i = 0; i < 4; i++) {
            float a = As[(tr + i) * 132 + k];
            acc0[i] = f4fma(a, b0, acc0[i]);
            acc1[i] = f4fma(a, b1, acc1[i]);
        }
    }
    #pragma unroll
    for (int i = 0; i < 4; i++) {
        int m = m0 + tr + i;
        if (m >= NB) continue;
        *(float4*)(g_hs + (size_t)m * NC + tc) = acc0[i];
        *(float4*)(g_hs + (size_t)m * NC + tc + 4) = acc1[i];
    }
}

// ---------------- 5a. build w(d) table: one warp per grid row -----------------
__global__ void __launch_bounds__(256) build_wtab(const float* __restrict__ Wr1,
                                                  const float* __restrict__ br1,
                                                  const float* __restrict__ Wr2) {
    extern __shared__ float sm[];
    float* Wr1s = sm;                 // 16*64
    float* br1s = Wr1s + 1024;        // 64
    float* Wr2s = br1s + 64;          // 64*256
    float* hids = Wr2s + 16384;       // 8*64
    int tid = threadIdx.x;
    for (int i = tid; i < 1024; i += 256) Wr1s[i] = Wr1[i];
    for (int i = tid; i < 64; i += 256) br1s[i] = br1[i];
    for (int i = tid; i < 16384; i += 256) Wr2s[i] = Wr2[i];
    __syncthreads();

    int warp = tid >> 5, lane = tid & 31;
    float* hid = hids + warp * 64;
    int row = blockIdx.x * 8 + warp;
    if (row > TBINS) return;
    float d = fmaxf(row * (5.0f / TBINS), 1e-6f);

    float rv = 0.0f;
    if (lane < 16) {
        float x = d * 0.2f;
        float fcut = 0.0f;
        if (x < 1.0f) {
            float x2 = x * x, x5 = x2 * x2 * x;
            fcut = 1.0f - 21.0f * x5 + 35.0f * x5 * x - 15.0f * x5 * x2;
        }
        float pref = 0.6324555320336759f / d * fcut;
        rv = pref * sinf((lane + 1) * (PI_F * 0.2f) * d);
    }
    float h0 = br1s[lane], h1 = br1s[lane + 32];
    #pragma unroll
    for (int k = 0; k < 16; k++) {
        float r = __shfl_sync(0xffffffffu, rv, k);
        h0 += r * Wr1s[k * 64 + lane];
        h1 += r * Wr1s[k * 64 + lane + 32];
    }
    h0 = h0 / (1.0f + __expf(-h0));
    h1 = h1 / (1.0f + __expf(-h1));
    __syncwarp();
    hid[lane] = h0;
    hid[lane + 32] = h1;
    __syncwarp();
    int c0 = lane * 4;
    float4 ws = make_float4(0, 0, 0, 0), wv = make_float4(0, 0, 0, 0);
    #pragma unroll 8
    for (int h = 0; h < 64; h++) {
        float hv = hid[h];
        ws = f4fma(hv, *(const float4*)(Wr2s + h * 256 + c0), ws);
        wv = f4fma(hv, *(const float4*)(Wr2s + h * 256 + 128 + c0), wv);
    }
    *(float4*)(g_wtab + (size_t)row * 256 + c0) = ws;
    *(float4*)(g_wtab + (size_t)row * 256 + 128 + c0) = wv;
}

// ---------------- 5b. edge apply (dst-sorted): warp per destination -----------
// Walks this dst's edge list, accumulates agg_s/agg_v in registers, writes each
// output row ONCE with plain stores. No atomics, no agg memsets.
__global__ void __launch_bounds__(256) edge_apply_sorted(const int* __restrict__ edges) {
    int t = blockIdx.x * blockDim.x + threadIdx.x;
    int d = t >> 5;
    if (d >= NB) return;
    int lane = t & 31;
    int c0 = lane * 4;
    int beg = g_off[d], end = g_off[d + 1];
    float4 as = make_float4(0, 0, 0, 0);
    float4 av0 = make_float4(0, 0, 0, 0);
    float4 av1 = make_float4(0, 0, 0, 0);
    float4 av2 = make_float4(0, 0, 0, 0);
    for (int i = beg; i < end; i++) {
        int e = g_perm[i];
        int s = edges[e];  // self-edges excluded at build time
        float dd = g_d[e];
        float tt = fminf(dd, 5.0f) * (TBINS / 5.0f);
        int idx = min((int)tt, TBINS - 1);
        float f = tt - (float)idx;
        const float* r0 = g_wtab + (size_t)idx * 256;
        float4 ws = f4lerp(*(const float4*)(r0 + c0),
                           *(const float4*)(r0 + 256 + c0), f);
        float4 wv = f4lerp(*(const float4*)(r0 + 128 + c0),
                           *(const float4*)(r0 + 384 + c0), f);
        float4 hs = *(const float4*)(g_hs + (size_t)s * NC + c0);
        as.x += ws.x * hs.x; as.y += ws.y * hs.y;
        as.z += ws.z * hs.z; as.w += ws.w * hs.w;
        float u0 = g_u[e * 3 + 0], u1 = g_u[e * 3 + 1], u2 = g_u[e * 3 + 2];
        const float* hvp = g_hv + (size_t)s * 384;
        float4 hv;
        hv = *(const float4*)(hvp + c0);
        av0.x += wv.x * (hv.x + hs.x * u0); av0.y += wv.y * (hv.y + hs.y * u0);
        av0.z += wv.z * (hv.z + hs.z * u0); av0.w += wv.w * (hv.w + hs.w * u0);
        hv = *(const float4*)(hvp + 128 + c0);
        av1.x += wv.x * (hv.x + hs.x * u1); av1.y += wv.y * (hv.y + hs.y * u1);
        av1.z += wv.z * (hv.z + hs.z * u1); av1.w += wv.w * (hv.w + hs.w * u1);
        hv = *(const float4*)(hvp + 256 + c0);
        av2.x += wv.x * (hv.x + hs.x * u2); av2.y += wv.y * (hv.y + hs.y * u2);
        av2.z += wv.z * (hv.z + hs.z * u2); av2.w += wv.w * (hv.w + hs.w * u2);
    }
    *(float4*)(g_aggs + (size_t)d * NC + c0) = as;
    float* avp = g_aggv + (size_t)d * 384;
    *(float4*)(avp + c0) = av0;
    *(float4*)(avp + 128 + c0) = av1;
    *(float4*)(avp + 256 + c0) = av2;
}

// ---------------- 6. node s-update GEMM --------------------------------------
__global__ void __launch_bounds__(256) gemm_s(const float* __restrict__ Wsl, int l,
                                              float* __restrict__ outB) {
    extern __shared__ float sm[];
    float* W0 = sm;
    float* W1 = sm + 16384;
    float* As = sm + 32768;  // 64*132
    const float* W2 = Wsl + 32768;
    int tid = threadIdx.x;
    for (int i = tid; i < 2 * 16384; i += 256) sm[i] = Wsl[i];
    int m0 = blockIdx.x * 64;
    for (int i = tid; i < 64 * 32; i += 256) {
        int r = i >> 5, kq = (i & 31) * 4;
        float4 v = make_float4(0, 0, 0, 0);
        int m = m0 + r;
        if (m < NB) v = *(const float4*)(g_aggs + (size_t)m * NC + kq);
        *(float4*)(As + r * 132 + kq) = v;
    }
    __syncthreads();
    int tr = (tid >> 4) << 2;
    int tc = (tid & 15) << 3;
    float4 acc0[4] = {}, acc1[4] = {};
    for (int k = 0; k < 128; k++) {
        float4 b00 = *(const float4*)(W0 + k * 128 + tc);
        float4 b01 = *(const float4*)(W0 + k * 128 + tc + 4);
        float4 b10 = *(const float4*)(W1 + k * 128 + tc);
        float4 b11 = *(const float4*)(W1 + k * 128 + tc + 4);
        float4 b20 = __ldg((const float4*)(W2 + k * 128 + tc));
        float4 b21 = __ldg((const float4*)(W2 + k * 128 + tc + 4));
        #pragma unroll
        for (int i = 0; i < 4; i++) {
            float a = As[(tr + i) * 132 + k];
            float a2 = a * a, a3 = a2 * a;
            acc0[i] = f4fma(a, b00, acc0[i]);
            acc0[i] = f4fma(a2, b10, acc0[i]);
            acc0[i] = f4fma(a3, b20, acc0[i]);
            acc1[i] = f4fma(a, b01, acc1[i]);
            acc1[i] = f4fma(a2, b11, acc1[i]);
            acc1[i] = f4fma(a3, b21, acc1[i]);
        }
    }
    #pragma unroll
    for (int i = 0; i < 4; i++) {
        int m = m0 + tr + i;
        if (m >= NB) continue;
        float* hsrow = g_hs + (size_t)m * NC + tc;
        float4 v0 = acc0[i], v1 = acc1[i];
        if (l) {
            v0 = f4add(v0, *(float4*)hsrow);
            v1 = f4add(v1, *(float4*)(hsrow + 4));
        }
        *(float4*)hsrow = v0;
        *(float4*)(hsrow + 4) = v1;
        float* fo = outB + (size_t)m * 1024 + l * 512 + tc;
        *(float4*)fo = v0;
        *(float4*)(fo + 4) = v1;
    }
}

// ---------------- 7. node v-update GEMM --------------------------------------
__global__ void __launch_bounds__(256) gemm_v(const float* __restrict__ Wvl,
                                              const float* __restrict__ wsvl, int l,
                                              float* __restrict__ outB) {
    extern __shared__ float sm[];
    float* Bs = sm;            // 128*128
    float* As = sm + 16384;    // 64*132
    __shared__ float wsvs[128];
    int tid = threadIdx.x;
    for (int i = tid; i < 16384; i += 256) Bs[i] = Wvl[i];
    if (tid < 128) wsvs[tid] = wsvl[tid];
    int m0 = blockIdx.x * 64;
    for (int i = tid; i < 64 * 32; i += 256) {
        int r = i >> 5, kq = (i & 31) * 4;
        float4 v = make_float4(0, 0, 0, 0);
        int m = m0 + r;
        if (m < NB * 3) v = *(const float4*)(g_aggv + (size_t)m * NC + kq);
        *(float4*)(As + r * 132 + kq) = v;
    }
    __syncthreads();
    int tr = (tid >> 4) << 2;
    int tc = (tid & 15) << 3;
    float4 acc0[4] = {}, acc1[4] = {};
    for (int k = 0; k < 128; k++) {
        float4 b0 = *(const float4*)(Bs + k * 128 + tc);
        float4 b1 = *(const float4*)(Bs + k * 128 + tc + 4);
        #pragma unroll
        for (int i = 0; i < 4; i++) {
            float a = As[(tr + i) * 132 + k];
            acc0[i] = f4fma(a, b0, acc0[i]);
            acc1[i] = f4fma(a, b1, acc1[i]);
        }
    }
    #pragma unroll
    for (int i = 0; i < 4; i++) {
        int m = m0 + tr + i;
        if (m >= NB * 3) continue;
        int n = m / 3;
        int x = m - 3 * n;
        float4 av0 = *(float4*)(As + (tr + i) * 132 + tc);
        float4 av1 = *(float4*)(As + (tr + i) * 132 + tc + 4);
        float4 as0 = *(const float4*)(g_aggs + (size_t)n * NC + tc);
        float4 as1 = *(const float4*)(g_aggs + (size_t)n * NC + tc + 4);
        float4 sv0 = *(const float4*)(wsvs + tc);
        float4 sv1 = *(const float4*)(wsvs + tc + 4);
        float4 r0 = acc0[i], r1 = acc1[i];
        r0.x += sv0.x * as0.x * av0.x; r0.y += sv0.y * as0.y * av0.y;
        r0.z += sv0.z * as0.z * av0.z; r0.w += sv0.w * as0.w * av0.w;
        r1.x += sv1.x * as1.x * av1.x; r1.y += sv1.y * as1.y * av1.y;
        r1.z += sv1.z * as1.z * av1.z; r1.w += sv1.w * as1.w * av1.w;
        float* hvrow = g_hv + (size_t)m * NC + tc;
        if (l) {
            r0 = f4add(r0, *(float4*)hvrow);
            r1 = f4add(r1, *(float4*)(hvrow + 4));
        }
        *(float4*)hvrow = r0;
        *(float4*)(hvrow + 4) = r1;
        // feats layout: 128 + c*3 + x
        float* fo = outB + (size_t)n * 1024 + l * 512 + 128 + x;
        fo[(tc + 0) * 3] = r0.x; fo[(tc + 1) * 3] = r0.y;
        fo[(tc + 2) * 3] = r0.z; fo[(tc + 3) * 3] = r0.w;
        fo[(tc + 4) * 3] = r1.x; fo[(tc + 5) * 3] = r1.y;
        fo[(tc + 6) * 3] = r1.z; fo[(tc + 7) * 3] = r1.w;
    }
}

// ---------------- 8. normalize rows + scatter to graphs ----------------------
__global__ void norm_block(float* __restrict__ outB, float* __restrict__ outC,
                           const int* __restrict__ batch_id) {
    int t = blockIdx.x * blockDim.x + threadIdx.x;
    int n = t >> 5;
    if (n >= NB) return;
    int lane = t & 31;
    float* row = outB + (size_t)n * 1024;
    float4 v[8];
    float ss = 0.0f;
    #pragma unroll
    for (int i = 0; i < 8; i++) {
        v[i] = *(float4*)(row + i * 128 + lane * 4);
        ss += v[i].x * v[i].x + v[i].y * v[i].y + v[i].z * v[i].z + v[i].w * v[i].w;
    }
    #pragma unroll
    for (int o = 16; o; o >>= 1) ss += __shfl_xor_sync(0xffffffffu, ss, o);
    float inv = 1.0f / fmaxf(sqrtf(ss), 1e-12f);
    int b = batch_id[n];
    float* grow = outC + (size_t)b * 1024;
    #pragma unroll
    for (int i = 0; i < 8; i++) {
        v[i] = f4scale(v[i], inv);
        *(float4*)(row + i * 128 + lane * 4) = v[i];
        red_add_v4(grow + i * 128 + lane * 4, v[i]);
    }
}

__global__ void norm_g(float* __restrict__ outC) {
    int t = blockIdx.x * blockDim.x + threadIdx.x;
    int n = t >> 5;
    if (n >= NG) return;
    int lane = t & 31;
    float* row = outC + (size_t)n * 1024;
    float4 v[8];
    float ss = 0.0f;
    #pragma unroll
    for (int i = 0; i < 8; i++) {
        v[i] = *(float4*)(row + i * 128 + lane * 4);
        ss += v[i].x * v[i].x + v[i].y * v[i].y + v[i].z * v[i].z + v[i].w * v[i].w;
    }
    #pragma unroll
    for (int o = 16; o; o >>= 1) ss += __shfl_xor_sync(0xffffffffu, ss, o);
    float inv = 1.0f / fmaxf(sqrtf(ss), 1e-12f);
    #pragma unroll
    for (int i = 0; i < 8; i++)
        *(float4*)(row + i * 128 + lane * 4) = f4scale(v[i], inv);
}

// ---------------- launch ------------------------------------------------------
extern "C" void kernel_launch(void* const* d_in, const int* in_sizes, int n_in,
                              void* d_out, int out_size) {
    const float* H       = (const float*)d_in[0];
    const float* Z       = (const float*)d_in[1];
    const float* W_embed = (const float*)d_in[2];
    const float* Wr1     = (const float*)d_in[3];
    const float* br1     = (const float*)d_in[4];
    const float* Wr2     = (const float*)d_in[5];
    const float* Ws      = (const float*)d_in[6];
    const float* Wv      = (const float*)d_in[7];
    const float* wsv     = (const float*)d_in[8];
    const int* block_id  = (const int*)d_in[9];
    const int* batch_id  = (const int*)d_in[10];
    const int* edges     = (const int*)d_in[11];

    float* outA = (float*)d_out;                    // Hb        [20000,128]
    float* outB = outA + (size_t)NB * NC;           // block_repr[20000,1024]
    float* outC = outB + (size_t)NB * 1024;         // graph_repr[512,1024]

    const int BT_SMEM = (1024 + 64 + 16384 + 8 * 64) * 4;           // 71936
    const int GS_SMEM = (2 * 16384 + 64 * 132) * 4;                 // 164864
    const int GV_SMEM = (16384 + 64 * 132) * 4;                     // 99328

    cudaFuncSetAttribute(build_wtab, cudaFuncAttributeMaxDynamicSharedMemorySize, BT_SMEM);
    cudaFuncSetAttribute(gemm_s,     cudaFuncAttributeMaxDynamicSharedMemorySize, GS_SMEM);
    cudaFuncSetAttribute(gemm_v,     cudaFuncAttributeMaxDynamicSharedMemorySize, GV_SMEM);
    cudaFuncSetAttribute(gemm_embed, cudaFuncAttributeMaxDynamicSharedMemorySize, GV_SMEM);

    void *pZb, *pcnt, *phv, *pdeg;
    cudaGetSymbolAddress(&pZb, g_Zb);
    cudaGetSymbolAddress(&pcnt, g_cnt);
    cudaGetSymbolAddress(&phv, g_hv);
    cudaGetSymbolAddress(&pdeg, g_deg);

    cudaMemsetAsync(outA, 0, (size_t)NB * NC * 4);
    cudaMemsetAsync(outC, 0, (size_t)NG * 1024 * 4);
    cudaMemsetAsync(pZb, 0, (size_t)NB * 3 * 4);
    cudaMemsetAsync(pcnt, 0, (size_t)NB * 4);
    cudaMemsetAsync(phv, 0, (size_t)NB * 384 * 4);
    cudaMemsetAsync(pdeg, 0, (size_t)NB * 4);

    atom_scatter<<<(NA * 32 + 255) / 256, 256>>>(H, Z, block_id, outA);
    finalize_blocks<<<(NB * 32 + 255) / 256, 256>>>(outA);
    gemm_embed<<<(NB + 63) / 64, 256, GV_SMEM>>>(outA, W_embed);
    edge_geom<<<(NE + 255) / 256, 256>>>(edges);
    scan_offsets<<<1, 256>>>();
    scatter_perm<<<(NE + 255) / 256, 256>>>(edges);

    for (int l = 0; l < 2; l++) {
        build_wtab<<<(TBINS + 1 + 7) / 8, 256, BT_SMEM>>>(Wr1 + l * 16 * 64,
                                                          br1 + l * 64,
                                                          Wr2 + l * 64 * 256);
        edge_apply_sorted<<<(NB * 32 + 255) / 256, 256>>>(edges);
        gemm_s<<<(NB + 63) / 64, 256, GS_SMEM>>>(Ws + (size_t)l * 3 * 16384, l, outB);
        gemm_v<<<(NB * 3 + 63) / 64, 256, GV_SMEM>>>(Wv + (size_t)l * 16384,
                                                     wsv + l * 128, l, outB);
    }

    norm_block<<<(NB * 32 + 255) / 256, 256>>>(outB, outC, batch_id);
    norm_g<<<(NG * 32 + 255) / 256, 256>>>(outC);
}

// round 14
// speedup vs baseline: 1.7685x; 1.0210x over previous
#include <cuda_runtime.h>
#include <math.h>
#include <stdint.h>

#define NB 20000
#define NA 80000
#define NE 320000
#define NC 128
#define NG 512
#define TBINS 16384
#define PI_F 3.14159265358979323846f

// ---------------- scratch (device globals; no allocation allowed) -------------
__device__ float g_Zb[NB * 3];
__device__ float g_cnt[NB];
__device__ float g_hs[NB * NC];            // h_s [n][c]
__device__ float g_hv[NB * 3 * NC];        // h_v [n][x][c]
__device__ float g_aggs[NB * NC];          // agg_s [n][c]
__device__ float g_aggv[NB * 3 * NC];      // agg_v [n][x][c]
__device__ float g_d[NE];
__device__ float g_u[NE * 3];
__device__ float g_wtab[(TBINS + 1) * 256]; // w(d) rows: [ws(128) | wv(128)]
__device__ int   g_deg[NB];
__device__ int   g_off[NB + 1];
__device__ int   g_cur[NB];
__device__ int   g_perm[NE];

// ---------------- helpers ----------------------------------------------------
__device__ __forceinline__ void red_add_v4(float* addr, float4 v) {
    asm volatile("red.global.add.v4.f32 [%0], {%1,%2,%3,%4};"
                 :: "l"(addr), "f"(v.x), "f"(v.y), "f"(v.z), "f"(v.w)
                 : "memory");
}
__device__ __forceinline__ float4 f4fma(float a, float4 b, float4 c) {
    c.x += a * b.x; c.y += a * b.y; c.z += a * b.z; c.w += a * b.w; return c;
}
__device__ __forceinline__ float4 f4add(float4 a, float4 b) {
    a.x += b.x; a.y += b.y; a.z += b.z; a.w += b.w; return a;
}
__device__ __forceinline__ float4 f4scale(float4 a, float s) {
    a.x *= s; a.y *= s; a.z *= s; a.w *= s; return a;
}
__device__ __forceinline__ float4 f4lerp(float4 a, float4 b, float f) {
    a.x += f * (b.x - a.x); a.y += f * (b.y - a.y);
    a.z += f * (b.z - a.z); a.w += f * (b.w - a.w); return a;
}

// ---------------- 1. atom -> block scatter (sums) -----------------------------
__global__ void atom_scatter(const float* __restrict__ H, const float* __restrict__ Z,
                             const int* __restrict__ bid, float* __restrict__ HbSum) {
    int t = blockIdx.x * blockDim.x + threadIdx.x;
    int a = t >> 5;
    if (a >= NA) return;
    int lane = t & 31;
    int b = bid[a];
    float4 v = *(const float4*)(H + (size_t)a * NC + lane * 4);
    red_add_v4(HbSum + (size_t)b * NC + lane * 4, v);
    if (lane < 3) atomicAdd(&g_Zb[b * 3 + lane], Z[a * 3 + lane]);
    if (lane == 0) atomicAdd(&g_cnt[b], 1.0f);
}

// ---------------- 2. finalize means ------------------------------------------
__global__ void finalize_blocks(float* __restrict__ Hb) {
    int t = blockIdx.x * blockDim.x + threadIdx.x;
    int b = t >> 5;
    if (b >= NB) return;
    int lane = t & 31;
    float inv = 1.0f / fmaxf(g_cnt[b], 1.0f);
    float4* p = (float4*)(Hb + (size_t)b * NC + lane * 4);
    *p = f4scale(*p, inv);
    if (lane < 3) g_Zb[b * 3 + lane] *= inv;
}

// ---------------- 3. edge geometry: d, u + degree histogram -------------------
__global__ void edge_geom(const int* __restrict__ edges) {
    int e = blockIdx.x * blockDim.x + threadIdx.x;
    if (e >= NE) return;
    int s = edges[e], d_ = edges[NE + e];
    float rx = g_Zb[d_ * 3 + 0] - g_Zb[s * 3 + 0];
    float ry = g_Zb[d_ * 3 + 1] - g_Zb[s * 3 + 1];
    float rz = g_Zb[d_ * 3 + 2] - g_Zb[s * 3 + 2];
    float d = sqrtf(rx * rx + ry * ry + rz * rz + 1e-12f);
    float invd = 1.0f / d;
    g_d[e] = d;
    g_u[e * 3 + 0] = rx * invd;
    g_u[e * 3 + 1] = ry * invd;
    g_u[e * 3 + 2] = rz * invd;
    if (s != d_) atomicAdd(&g_deg[d_], 1);   // masked edges never enter lists
}

// ---------------- 3b. exclusive scan of degrees (single CTA) ------------------
__global__ void scan_offsets() {
    __shared__ int partial[256];
    const int CH = (NB + 255) / 256;  // 79
    int t = threadIdx.x;
    int base = t * CH;
    int sum = 0;
    for (int i = 0; i < CH; i++) {
        int idx = base + i;
        if (idx < NB) sum += g_deg[idx];
    }
    partial[t] = sum;
    __syncthreads();
    for (int off = 1; off < 256; off <<= 1) {
        int v = 0;
        if (t >= off) v = partial[t - off];
        __syncthreads();
        if (t >= off) partial[t] += v;
        __syncthreads();
    }
    int run = (t == 0) ? 0 : partial[t - 1];
    for (int i = 0; i < CH; i++) {
        int idx = base + i;
        if (idx < NB) {
            g_off[idx] = run;
            g_cur[idx] = run;
            run += g_deg[idx];
        }
    }
    if (t == 255) g_off[NB] = run;
}

// ---------------- 3c. scatter edges into dst-sorted order ---------------------
__global__ void scatter_perm(const int* __restrict__ edges) {
    int e = blockIdx.x * blockDim.x + threadIdx.x;
    if (e >= NE) return;
    int s = edges[e], dst = edges[NE + e];
    if (s == dst) return;
    int pos = atomicAdd(&g_cur[dst], 1);
    g_perm[pos] = e;
}

// ---------------- 4. embed GEMM: h_s = Hb @ W_embed --------------------------
__global__ void __launch_bounds__(256) gemm_embed(const float* __restrict__ A,
                                                  const float* __restrict__ B) {
    extern __shared__ float sm[];
    float* Bs = sm;            // 128*128
    float* As = sm + 16384;    // 64*132
    int tid = threadIdx.x;
    for (int i = tid; i < 16384; i += 256) Bs[i] = B[i];
    int m0 = blockIdx.x * 64;
    for (int i = tid; i < 64 * 32; i += 256) {
        int r = i >> 5, kq = (i & 31) * 4;
        float4 v = make_float4(0, 0, 0, 0);
        int m = m0 + r;
        if (m < NB) v = *(const float4*)(A + (size_t)m * NC + kq);
        *(float4*)(As + r * 132 + kq) = v;
    }
    __syncthreads();
    int tr = (tid >> 4) << 2;
    int tc = (tid & 15) << 3;
    float4 acc0[4] = {}, acc1[4] = {};
    for (int k = 0; k < 128; k++) {
        float4 b0 = *(const float4*)(Bs + k * 128 + tc);
        float4 b1 = *(const float4*)(Bs + k * 128 + tc + 4);
        #pragma unroll
        for (int i = 0; i < 4; i++) {
            float a = As[(tr + i) * 132 + k];
            acc0[i] = f4fma(a, b0, acc0[i]);
            acc1[i] = f4fma(a, b1, acc1[i]);
        }
    }
    #pragma unroll
    for (int i = 0; i < 4; i++) {
        int m = m0 + tr + i;
        if (m >= NB) continue;
        *(float4*)(g_hs + (size_t)m * NC + tc) = acc0[i];
        *(float4*)(g_hs + (size_t)m * NC + tc + 4) = acc1[i];
    }
}

// ---------------- 5a. build w(d) table: one warp per grid row -----------------
__global__ void __launch_bounds__(256) build_wtab(const float* __restrict__ Wr1,
                                                  const float* __restrict__ br1,
                                                  const float* __restrict__ Wr2) {
    extern __shared__ float sm[];
    float* Wr1s = sm;                 // 16*64
    float* br1s = Wr1s + 1024;        // 64
    float* Wr2s = br1s + 64;          // 64*256
    float* hids = Wr2s + 16384;       // 8*64
    int tid = threadIdx.x;
    for (int i = tid; i < 1024; i += 256) Wr1s[i] = Wr1[i];
    for (int i = tid; i < 64; i += 256) br1s[i] = br1[i];
    for (int i = tid; i < 16384; i += 256) Wr2s[i] = Wr2[i];
    __syncthreads();

    int warp = tid >> 5, lane = tid & 31;
    float* hid = hids + warp * 64;
    int row = blockIdx.x * 8 + warp;
    if (row > TBINS) return;
    float d = fmaxf(row * (5.0f / TBINS), 1e-6f);

    float rv = 0.0f;
    if (lane < 16) {
        float x = d * 0.2f;
        float fcut = 0.0f;
        if (x < 1.0f) {
            float x2 = x * x, x5 = x2 * x2 * x;
            fcut = 1.0f - 21.0f * x5 + 35.0f * x5 * x - 15.0f * x5 * x2;
        }
        float pref = 0.6324555320336759f / d * fcut;
        rv = pref * sinf((lane + 1) * (PI_F * 0.2f) * d);
    }
    float h0 = br1s[lane], h1 = br1s[lane + 32];
    #pragma unroll
    for (int k = 0; k < 16; k++) {
        float r = __shfl_sync(0xffffffffu, rv, k);
        h0 += r * Wr1s[k * 64 + lane];
        h1 += r * Wr1s[k * 64 + lane + 32];
    }
    h0 = h0 / (1.0f + __expf(-h0));
    h1 = h1 / (1.0f + __expf(-h1));
    __syncwarp();
    hid[lane] = h0;
    hid[lane + 32] = h1;
    __syncwarp();
    int c0 = lane * 4;
    float4 ws = make_float4(0, 0, 0, 0), wv = make_float4(0, 0, 0, 0);
    #pragma unroll 8
    for (int h = 0; h < 64; h++) {
        float hv = hid[h];
        ws = f4fma(hv, *(const float4*)(Wr2s + h * 256 + c0), ws);
        wv = f4fma(hv, *(const float4*)(Wr2s + h * 256 + 128 + c0), wv);
    }
    *(float4*)(g_wtab + (size_t)row * 256 + c0) = ws;
    *(float4*)(g_wtab + (size_t)row * 256 + 128 + c0) = wv;
}

// ---------------- 5b. edge apply (dst-sorted, staged indices) -----------------
// Warp per destination. Lanes cooperatively load up to 32 edges' indices/d/u
// into per-warp SMEM (breaking the perm->edges->gather pointer chase), then the
// accumulation loop issues gathers with addresses known up front (high MLP).
#define CHUNK 32
__global__ void __launch_bounds__(256) edge_apply_sorted(const int* __restrict__ edges) {
    __shared__ int   sS[8][CHUNK];
    __shared__ float dS[8][CHUNK];
    __shared__ float uS[8][3 * CHUNK];
    int t = blockIdx.x * blockDim.x + threadIdx.x;
    int d = t >> 5;
    if (d >= NB) return;  // whole warp exits together (d is per-warp)
    int w = threadIdx.x >> 5;
    int lane = t & 31;
    int c0 = lane * 4;
    int beg = g_off[d], end = g_off[d + 1];
    float4 as  = make_float4(0, 0, 0, 0);
    float4 av0 = make_float4(0, 0, 0, 0);
    float4 av1 = make_float4(0, 0, 0, 0);
    float4 av2 = make_float4(0, 0, 0, 0);
    for (int base = beg; base < end; base += CHUNK) {
        int cnt = min(CHUNK, end - base);
        if (lane < cnt) {
            int e = g_perm[base + lane];
            sS[w][lane] = edges[e];
            dS[w][lane] = g_d[e];
            uS[w][lane] = g_u[e * 3 + 0];
            uS[w][CHUNK + lane] = g_u[e * 3 + 1];
            uS[w][2 * CHUNK + lane] = g_u[e * 3 + 2];
        }
        __syncwarp();
        #pragma unroll 2
        for (int j = 0; j < cnt; j++) {
            int s = sS[w][j];
            float dd = dS[w][j];
            float tt = fminf(dd, 5.0f) * (TBINS / 5.0f);
            int idx = min((int)tt, TBINS - 1);
            float f = tt - (float)idx;
            const float* r0 = g_wtab + (size_t)idx * 256;
            float4 ws = f4lerp(*(const float4*)(r0 + c0),
                               *(const float4*)(r0 + 256 + c0), f);
            float4 wv = f4lerp(*(const float4*)(r0 + 128 + c0),
                               *(const float4*)(r0 + 384 + c0), f);
            float4 hs = *(const float4*)(g_hs + (size_t)s * NC + c0);
            as.x += ws.x * hs.x; as.y += ws.y * hs.y;
            as.z += ws.z * hs.z; as.w += ws.w * hs.w;
            float u0 = uS[w][j], u1 = uS[w][CHUNK + j], u2 = uS[w][2 * CHUNK + j];
            const float* hvp = g_hv + (size_t)s * 384;
            float4 hv;
            hv = *(const float4*)(hvp + c0);
            av0.x += wv.x * (hv.x + hs.x * u0); av0.y += wv.y * (hv.y + hs.y * u0);
            av0.z += wv.z * (hv.z + hs.z * u0); av0.w += wv.w * (hv.w + hs.w * u0);
            hv = *(const float4*)(hvp + 128 + c0);
            av1.x += wv.x * (hv.x + hs.x * u1); av1.y += wv.y * (hv.y + hs.y * u1);
            av1.z += wv.z * (hv.z + hs.z * u1); av1.w += wv.w * (hv.w + hs.w * u1);
            hv = *(const float4*)(hvp + 256 + c0);
            av2.x += wv.x * (hv.x + hs.x * u2); av2.y += wv.y * (hv.y + hs.y * u2);
            av2.z += wv.z * (hv.z + hs.z * u2); av2.w += wv.w * (hv.w + hs.w * u2);
        }
        __syncwarp();
    }
    *(float4*)(g_aggs + (size_t)d * NC + c0) = as;
    float* avp = g_aggv + (size_t)d * 384;
    *(float4*)(avp + c0) = av0;
    *(float4*)(avp + 128 + c0) = av1;
    *(float4*)(avp + 256 + c0) = av2;
}

// ---------------- 6. node s-update GEMM --------------------------------------
__global__ void __launch_bounds__(256) gemm_s(const float* __restrict__ Wsl, int l,
                                              float* __restrict__ outB) {
    extern __shared__ float sm[];
    float* W0 = sm;
    float* W1 = sm + 16384;
    float* As = sm + 32768;  // 64*132
    const float* W2 = Wsl + 32768;
    int tid = threadIdx.x;
    for (int i = tid; i < 2 * 16384; i += 256) sm[i] = Wsl[i];
    int m0 = blockIdx.x * 64;
    for (int i = tid; i < 64 * 32; i += 256) {
        int r = i >> 5, kq = (i & 31) * 4;
        float4 v = make_float4(0, 0, 0, 0);
        int m = m0 + r;
        if (m < NB) v = *(const float4*)(g_aggs + (size_t)m * NC + kq);
        *(float4*)(As + r * 132 + kq) = v;
    }
    __syncthreads();
    int tr = (tid >> 4) << 2;
    int tc = (tid & 15) << 3;
    float4 acc0[4] = {}, acc1[4] = {};
    for (int k = 0; k < 128; k++) {
        float4 b00 = *(const float4*)(W0 + k * 128 + tc);
        float4 b01 = *(const float4*)(W0 + k * 128 + tc + 4);
        float4 b10 = *(const float4*)(W1 + k * 128 + tc);
        float4 b11 = *(const float4*)(W1 + k * 128 + tc + 4);
        float4 b20 = __ldg((const float4*)(W2 + k * 128 + tc));
        float4 b21 = __ldg((const float4*)(W2 + k * 128 + tc + 4));
        #pragma unroll
        for (int i = 0; i < 4; i++) {
            float a = As[(tr + i) * 132 + k];
            float a2 = a * a, a3 = a2 * a;
            acc0[i] = f4fma(a, b00, acc0[i]);
            acc0[i] = f4fma(a2, b10, acc0[i]);
            acc0[i] = f4fma(a3, b20, acc0[i]);
            acc1[i] = f4fma(a, b01, acc1[i]);
            acc1[i] = f4fma(a2, b11, acc1[i]);
            acc1[i] = f4fma(a3, b21, acc1[i]);
        }
    }
    #pragma unroll
    for (int i = 0; i < 4; i++) {
        int m = m0 + tr + i;
        if (m >= NB) continue;
        float* hsrow = g_hs + (size_t)m * NC + tc;
        float4 v0 = acc0[i], v1 = acc1[i];
        if (l) {
            v0 = f4add(v0, *(float4*)hsrow);
            v1 = f4add(v1, *(float4*)(hsrow + 4));
        }
        *(float4*)hsrow = v0;
        *(float4*)(hsrow + 4) = v1;
        float* fo = outB + (size_t)m * 1024 + l * 512 + tc;
        *(float4*)fo = v0;
        *(float4*)(fo + 4) = v1;
    }
}

// ---------------- 7. node v-update GEMM --------------------------------------
__global__ void __launch_bounds__(256) gemm_v(const float* __restrict__ Wvl,
                                              const float* __restrict__ wsvl, int l,
                                              float* __restrict__ outB) {
    extern __shared__ float sm[];
    float* Bs = sm;            // 128*128
    float* As = sm + 16384;    // 64*132
    __shared__ float wsvs[128];
    int tid = threadIdx.x;
    for (int i = tid; i < 16384; i += 256) Bs[i] = Wvl[i];
    if (tid < 128) wsvs[tid] = wsvl[tid];
    int m0 = blockIdx.x * 64;
    for (int i = tid; i < 64 * 32; i += 256) {
        int r = i >> 5, kq = (i & 31) * 4;
        float4 v = make_float4(0, 0, 0, 0);
        int m = m0 + r;
        if (m < NB * 3) v = *(const float4*)(g_aggv + (size_t)m * NC + kq);
        *(float4*)(As + r * 132 + kq) = v;
    }
    __syncthreads();
    int tr = (tid >> 4) << 2;
    int tc = (tid & 15) << 3;
    float4 acc0[4] = {}, acc1[4] = {};
    for (int k = 0; k < 128; k++) {
        float4 b0 = *(const float4*)(Bs + k * 128 + tc);
        float4 b1 = *(const float4*)(Bs + k * 128 + tc + 4);
        #pragma unroll
        for (int i = 0; i < 4; i++) {
            float a = As[(tr + i) * 132 + k];
            acc0[i] = f4fma(a, b0, acc0[i]);
            acc1[i] = f4fma(a, b1, acc1[i]);
        }
    }
    #pragma unroll
    for (int i = 0; i < 4; i++) {
        int m = m0 + tr + i;
        if (m >= NB * 3) continue;
        int n = m / 3;
        int x = m - 3 * n;
        float4 av0 = *(float4*)(As + (tr + i) * 132 + tc);
        float4 av1 = *(float4*)(As + (tr + i) * 132 + tc + 4);
        float4 as0 = *(const float4*)(g_aggs + (size_t)n * NC + tc);
        float4 as1 = *(const float4*)(g_aggs + (size_t)n * NC + tc + 4);
        float4 sv0 = *(const float4*)(wsvs + tc);
        float4 sv1 = *(const float4*)(wsvs + tc + 4);
        float4 r0 = acc0[i], r1 = acc1[i];
        r0.x += sv0.x * as0.x * av0.x; r0.y += sv0.y * as0.y * av0.y;
        r0.z += sv0.z * as0.z * av0.z; r0.w += sv0.w * as0.w * av0.w;
        r1.x += sv1.x * as1.x * av1.x; r1.y += sv1.y * as1.y * av1.y;
        r1.z += sv1.z * as1.z * av1.z; r1.w += sv1.w * as1.w * av1.w;
        float* hvrow = g_hv + (size_t)m * NC + tc;
        if (l) {
            r0 = f4add(r0, *(float4*)hvrow);
            r1 = f4add(r1, *(float4*)(hvrow + 4));
        }
        *(float4*)hvrow = r0;
        *(float4*)(hvrow + 4) = r1;
        // feats layout: 128 + c*3 + x
        float* fo = outB + (size_t)n * 1024 + l * 512 + 128 + x;
        fo[(tc + 0) * 3] = r0.x; fo[(tc + 1) * 3] = r0.y;
        fo[(tc + 2) * 3] = r0.z; fo[(tc + 3) * 3] = r0.w;
        fo[(tc + 4) * 3] = r1.x; fo[(tc + 5) * 3] = r1.y;
        fo[(tc + 6) * 3] = r1.z; fo[(tc + 7) * 3] = r1.w;
    }
}

// ---------------- 8. normalize rows + scatter to graphs ----------------------
__global__ void norm_block(float* __restrict__ outB, float* __restrict__ outC,
                           const int* __restrict__ batch_id) {
    int t = blockIdx.x * blockDim.x + threadIdx.x;
    int n = t >> 5;
    if (n >= NB) return;
    int lane = t & 31;
    float* row = outB + (size_t)n * 1024;
    float4 v[8];
    float ss = 0.0f;
    #pragma unroll
    for (int i = 0; i < 8; i++) {
        v[i] = *(float4*)(row + i * 128 + lane * 4);
        ss += v[i].x * v[i].x + v[i].y * v[i].y + v[i].z * v[i].z + v[i].w * v[i].w;
    }
    #pragma unroll
    for (int o = 16; o; o >>= 1) ss += __shfl_xor_sync(0xffffffffu, ss, o);
    float inv = 1.0f / fmaxf(sqrtf(ss), 1e-12f);
    int b = batch_id[n];
    float* grow = outC + (size_t)b * 1024;
    #pragma unroll
    for (int i = 0; i < 8; i++) {
        v[i] = f4scale(v[i], inv);
        *(float4*)(row + i * 128 + lane * 4) = v[i];
        red_add_v4(grow + i * 128 + lane * 4, v[i]);
    }
}

__global__ void norm_g(float* __restrict__ outC) {
    int t = blockIdx.x * blockDim.x + threadIdx.x;
    int n = t >> 5;
    if (n >= NG) return;
    int lane = t & 31;
    float* row = outC + (size_t)n * 1024;
    float4 v[8];
    float ss = 0.0f;
    #pragma unroll
    for (int i = 0; i < 8; i++) {
        v[i] = *(float4*)(row + i * 128 + lane * 4);
        ss += v[i].x * v[i].x + v[i].y * v[i].y + v[i].z * v[i].z + v[i].w * v[i].w;
    }
    #pragma unroll
    for (int o = 16; o; o >>= 1) ss += __shfl_xor_sync(0xffffffffu, ss, o);
    float inv = 1.0f / fmaxf(sqrtf(ss), 1e-12f);
    #pragma unroll
    for (int i = 0; i < 8; i++)
        *(float4*)(row + i * 128 + lane * 4) = f4scale(v[i], inv);
}

// ---------------- launch ------------------------------------------------------
extern "C" void kernel_launch(void* const* d_in, const int* in_sizes, int n_in,
                              void* d_out, int out_size) {
    const float* H       = (const float*)d_in[0];
    const float* Z       = (const float*)d_in[1];
    const float* W_embed = (const float*)d_in[2];
    const float* Wr1     = (const float*)d_in[3];
    const float* br1     = (const float*)d_in[4];
    const float* Wr2     = (const float*)d_in[5];
    const float* Ws      = (const float*)d_in[6];
    const float* Wv      = (const float*)d_in[7];
    const float* wsv     = (const float*)d_in[8];
    const int* block_id  = (const int*)d_in[9];
    const int* batch_id  = (const int*)d_in[10];
    const int* edges     = (const int*)d_in[11];

    float* outA = (float*)d_out;                    // Hb        [20000,128]
    float* outB = outA + (size_t)NB * NC;           // block_repr[20000,1024]
    float* outC = outB + (size_t)NB * 1024;         // graph_repr[512,1024]

    const int BT_SMEM = (1024 + 64 + 16384 + 8 * 64) * 4;           // 71936
    const int GS_SMEM = (2 * 16384 + 64 * 132) * 4;                 // 164864
    const int GV_SMEM = (16384 + 64 * 132) * 4;                     // 99328

    cudaFuncSetAttribute(build_wtab, cudaFuncAttributeMaxDynamicSharedMemorySize, BT_SMEM);
    cudaFuncSetAttribute(gemm_s,     cudaFuncAttributeMaxDynamicSharedMemorySize, GS_SMEM);
    cudaFuncSetAttribute(gemm_v,     cudaFuncAttributeMaxDynamicSharedMemorySize, GV_SMEM);
    cudaFuncSetAttribute(gemm_embed, cudaFuncAttributeMaxDynamicSharedMemorySize, GV_SMEM);

    void *pZb, *pcnt, *phv, *pdeg;
    cudaGetSymbolAddress(&pZb, g_Zb);
    cudaGetSymbolAddress(&pcnt, g_cnt);
    cudaGetSymbolAddress(&phv, g_hv);
    cudaGetSymbolAddress(&pdeg, g_deg);

    cudaMemsetAsync(outA, 0, (size_t)NB * NC * 4);
    cudaMemsetAsync(outC, 0, (size_t)NG * 1024 * 4);
    cudaMemsetAsync(pZb, 0, (size_t)NB * 3 * 4);
    cudaMemsetAsync(pcnt, 0, (size_t)NB * 4);
    cudaMemsetAsync(phv, 0, (size_t)NB * 384 * 4);
    cudaMemsetAsync(pdeg, 0, (size_t)NB * 4);

    atom_scatter<<<(NA * 32 + 255) / 256, 256>>>(H, Z, block_id, outA);
    finalize_blocks<<<(NB * 32 + 255) / 256, 256>>>(outA);
    gemm_embed<<<(NB + 63) / 64, 256, GV_SMEM>>>(outA, W_embed);
    edge_geom<<<(NE + 255) / 256, 256>>>(edges);
    scan_offsets<<<1, 256>>>();
    scatter_perm<<<(NE + 255) / 256, 256>>>(edges);

    for (int l = 0; l < 2; l++) {
        build_wtab<<<(TBINS + 1 + 7) / 8, 256, BT_SMEM>>>(Wr1 + l * 16 * 64,
                                                          br1 + l * 64,
                                                          Wr2 + l * 64 * 256);
        edge_apply_sorted<<<(NB * 32 + 255) / 256, 256>>>(edges);
        gemm_s<<<(NB + 63) / 64, 256, GS_SMEM>>>(Ws + (size_t)l * 3 * 16384, l, outB);
        gemm_v<<<(NB * 3 + 63) / 64, 256, GV_SMEM>>>(Wv + (size_t)l * 16384,
                                                     wsv + l * 128, l, outB);
    }

    norm_block<<<(NB * 32 + 255) / 256, 256>>>(outB, outC, batch_id);
    norm_g<<<(NG * 32 + 255) / 256, 256>>>(outC);
}

// round 15
// speedup vs baseline: 1.8085x; 1.0227x over previous
#include <cuda_runtime.h>
#include <math.h>
#include <stdint.h>

#define NB 20000
#define NA 80000
#define NE 320000
#define NC 128
#define NG 512
#define TBINS 16384
#define TROWS (TBINS + 1)
#define PI_F 3.14159265358979323846f

// ---------------- scratch (device globals; no allocation allowed) -------------
__device__ float g_Zb[NB * 3];
__device__ float g_cnt[NB];
__device__ float g_hs[NB * NC];            // h_s [n][c]
__device__ float g_hv[NB * 3 * NC];        // h_v [n][x][c]
__device__ float g_aggs[NB * NC];          // agg_s [n][c]
__device__ float g_aggv[NB * 3 * NC];      // agg_v [n][x][c]
__device__ float g_d[NE];
__device__ float g_u[NE * 3];
__device__ float g_wtab[2 * TROWS * 256];  // both layers: [l][row][ws|wv]
__device__ int   g_deg[NB];
__device__ int   g_off[NB + 1];
__device__ int   g_cur[NB];
__device__ int   g_perm[NE];

// ---------------- helpers ----------------------------------------------------
__device__ __forceinline__ void red_add_v4(float* addr, float4 v) {
    asm volatile("red.global.add.v4.f32 [%0], {%1,%2,%3,%4};"
                 :: "l"(addr), "f"(v.x), "f"(v.y), "f"(v.z), "f"(v.w)
                 : "memory");
}
__device__ __forceinline__ float4 f4fma(float a, float4 b, float4 c) {
    c.x += a * b.x; c.y += a * b.y; c.z += a * b.z; c.w += a * b.w; return c;
}
__device__ __forceinline__ float4 f4add(float4 a, float4 b) {
    a.x += b.x; a.y += b.y; a.z += b.z; a.w += b.w; return a;
}
__device__ __forceinline__ float4 f4scale(float4 a, float s) {
    a.x *= s; a.y *= s; a.z *= s; a.w *= s; return a;
}
__device__ __forceinline__ float4 f4lerp(float4 a, float4 b, float f) {
    a.x += f * (b.x - a.x); a.y += f * (b.y - a.y);
    a.z += f * (b.z - a.z); a.w += f * (b.w - a.w); return a;
}

// ---------------- 1. atom -> block scatter (sums) -----------------------------
__global__ void atom_scatter(const float* __restrict__ H, const float* __restrict__ Z,
                             const int* __restrict__ bid, float* __restrict__ HbSum) {
    int t = blockIdx.x * blockDim.x + threadIdx.x;
    int a = t >> 5;
    if (a >= NA) return;
    int lane = t & 31;
    int b = bid[a];
    float4 v = *(const float4*)(H + (size_t)a * NC + lane * 4);
    red_add_v4(HbSum + (size_t)b * NC + lane * 4, v);
    if (lane < 3) atomicAdd(&g_Zb[b * 3 + lane], Z[a * 3 + lane]);
    if (lane == 0) atomicAdd(&g_cnt[b], 1.0f);
}

// ---------------- 2. finalize means ------------------------------------------
__global__ void finalize_blocks(float* __restrict__ Hb) {
    int t = blockIdx.x * blockDim.x + threadIdx.x;
    int b = t >> 5;
    if (b >= NB) return;
    int lane = t & 31;
    float inv = 1.0f / fmaxf(g_cnt[b], 1.0f);
    float4* p = (float4*)(Hb + (size_t)b * NC + lane * 4);
    *p = f4scale(*p, inv);
    if (lane < 3) g_Zb[b * 3 + lane] *= inv;
}

// ---------------- 3. edge geometry: d, u + degree histogram -------------------
__global__ void edge_geom(const int* __restrict__ edges) {
    int e = blockIdx.x * blockDim.x + threadIdx.x;
    if (e >= NE) return;
    int s = edges[e], d_ = edges[NE + e];
    float rx = g_Zb[d_ * 3 + 0] - g_Zb[s * 3 + 0];
    float ry = g_Zb[d_ * 3 + 1] - g_Zb[s * 3 + 1];
    float rz = g_Zb[d_ * 3 + 2] - g_Zb[s * 3 + 2];
    float d = sqrtf(rx * rx + ry * ry + rz * rz + 1e-12f);
    float invd = 1.0f / d;
    g_d[e] = d;
    g_u[e * 3 + 0] = rx * invd;
    g_u[e * 3 + 1] = ry * invd;
    g_u[e * 3 + 2] = rz * invd;
    if (s != d_) atomicAdd(&g_deg[d_], 1);   // masked edges never enter lists
}

// ---------------- 3b. exclusive scan of degrees (single CTA) ------------------
__global__ void scan_offsets() {
    __shared__ int partial[256];
    const int CH = (NB + 255) / 256;  // 79
    int t = threadIdx.x;
    int base = t * CH;
    int sum = 0;
    for (int i = 0; i < CH; i++) {
        int idx = base + i;
        if (idx < NB) sum += g_deg[idx];
    }
    partial[t] = sum;
    __syncthreads();
    for (int off = 1; off < 256; off <<= 1) {
        int v = 0;
        if (t >= off) v = partial[t - off];
        __syncthreads();
        if (t >= off) partial[t] += v;
        __syncthreads();
    }
    int run = (t == 0) ? 0 : partial[t - 1];
    for (int i = 0; i < CH; i++) {
        int idx = base + i;
        if (idx < NB) {
            g_off[idx] = run;
            g_cur[idx] = run;
            run += g_deg[idx];
        }
    }
    if (t == 255) g_off[NB] = run;
}

// ---------------- 3c. scatter edges into dst-sorted order ---------------------
__global__ void scatter_perm(const int* __restrict__ edges) {
    int e = blockIdx.x * blockDim.x + threadIdx.x;
    if (e >= NE) return;
    int s = edges[e], dst = edges[NE + e];
    if (s == dst) return;
    int pos = atomicAdd(&g_cur[dst], 1);
    g_perm[pos] = e;
}

// ---------------- 4. embed GEMM: h_s = Hb @ W_embed --------------------------
__global__ void __launch_bounds__(256) gemm_embed(const float* __restrict__ A,
                                                  const float* __restrict__ B) {
    extern __shared__ float sm[];
    float* Bs = sm;            // 128*128
    float* As = sm + 16384;    // 64*132
    int tid = threadIdx.x;
    for (int i = tid; i < 16384; i += 256) Bs[i] = B[i];
    int m0 = blockIdx.x * 64;
    for (int i = tid; i < 64 * 32; i += 256) {
        int r = i >> 5, kq = (i & 31) * 4;
        float4 v = make_float4(0, 0, 0, 0);
        int m = m0 + r;
        if (m < NB) v = *(const float4*)(A + (size_t)m * NC + kq);
        *(float4*)(As + r * 132 + kq) = v;
    }
    __syncthreads();
    int tr = (tid >> 4) << 2;
    int tc = (tid & 15) << 3;
    float4 acc0[4] = {}, acc1[4] = {};
    for (int k = 0; k < 128; k++) {
        float4 b0 = *(const float4*)(Bs + k * 128 + tc);
        float4 b1 = *(const float4*)(Bs + k * 128 + tc + 4);
        #pragma unroll
        for (int i = 0; i < 4; i++) {
            float a = As[(tr + i) * 132 + k];
            acc0[i] = f4fma(a, b0, acc0[i]);
            acc1[i] = f4fma(a, b1, acc1[i]);
        }
    }
    #pragma unroll
    for (int i = 0; i < 4; i++) {
        int m = m0 + tr + i;
        if (m >= NB) continue;
        *(float4*)(g_hs + (size_t)m * NC + tc) = acc0[i];
        *(float4*)(g_hs + (size_t)m * NC + tc + 4) = acc1[i];
    }
}

// ---------------- 5a. build w(d) tables for BOTH layers -----------------------
// One warp per (layer, grid row). blockIdx covers 2*TROWS rows.
__global__ void __launch_bounds__(256) build_wtab(const float* __restrict__ Wr1,
                                                  const float* __restrict__ br1,
                                                  const float* __restrict__ Wr2) {
    extern __shared__ float sm[];
    float* Wr1s = sm;                 // 16*64
    float* br1s = Wr1s + 1024;        // 64
    float* Wr2s = br1s + 64;          // 64*256
    float* hids = Wr2s + 16384;       // 8*64
    int tid = threadIdx.x;
    int warp = tid >> 5, lane = tid & 31;
    int gr = blockIdx.x * 8 + warp;   // global row in [0, 2*TROWS)
    int l = (blockIdx.x * 8) >= TROWS ? 1 : 0;  // whole CTA same layer (TROWS+7)/8*8 aligned? handle per-warp:
    // per-warp layer/row (TROWS not multiple of 8, so compute per warp)
    int row, lay;
    if (gr < TROWS) { lay = 0; row = gr; }
    else            { lay = 1; row = gr - TROWS; }
    // stage this CTA's layer weights: all warps in a CTA may span the boundary
    // only for one CTA; to stay simple stage BOTH layers? too big. Instead:
    // stage layer of warp 0 and let boundary-CTA warps of the other layer
    // recompute from global via __ldg (rare: at most 1 CTA).
    int cta_lay = (blockIdx.x * 8 < TROWS) ? 0 : 1;
    for (int i = tid; i < 1024; i += 256) Wr1s[i] = Wr1[cta_lay * 1024 + i];
    for (int i = tid; i < 64; i += 256) br1s[i] = br1[cta_lay * 64 + i];
    for (int i = tid; i < 16384; i += 256) Wr2s[i] = Wr2[cta_lay * 16384 + i];
    __syncthreads();
    if (gr >= 2 * TROWS) return;
    bool inS = (lay == cta_lay);
    const float* Wr1p = inS ? Wr1s : (Wr1 + lay * 1024);
    const float* br1p = inS ? br1s : (br1 + lay * 64);
    const float* Wr2p = inS ? Wr2s : (Wr2 + lay * 16384);

    float* hid = hids + warp * 64;
    float d = fmaxf(row * (5.0f / TBINS), 1e-6f);
    float rv = 0.0f;
    if (lane < 16) {
        float x = d * 0.2f;
        float fcut = 0.0f;
        if (x < 1.0f) {
            float x2 = x * x, x5 = x2 * x2 * x;
            fcut = 1.0f - 21.0f * x5 + 35.0f * x5 * x - 15.0f * x5 * x2;
        }
        float pref = 0.6324555320336759f / d * fcut;
        rv = pref * sinf((lane + 1) * (PI_F * 0.2f) * d);
    }
    float h0 = br1p[lane], h1 = br1p[lane + 32];
    #pragma unroll
    for (int k = 0; k < 16; k++) {
        float r = __shfl_sync(0xffffffffu, rv, k);
        h0 += r * Wr1p[k * 64 + lane];
        h1 += r * Wr1p[k * 64 + lane + 32];
    }
    h0 = h0 / (1.0f + __expf(-h0));
    h1 = h1 / (1.0f + __expf(-h1));
    __syncwarp();
    hid[lane] = h0;
    hid[lane + 32] = h1;
    __syncwarp();
    int c0 = lane * 4;
    float4 ws = make_float4(0, 0, 0, 0), wv = make_float4(0, 0, 0, 0);
    #pragma unroll 8
    for (int h = 0; h < 64; h++) {
        float hv = hid[h];
        ws = f4fma(hv, *(const float4*)(Wr2p + h * 256 + c0), ws);
        wv = f4fma(hv, *(const float4*)(Wr2p + h * 256 + 128 + c0), wv);
    }
    float* out = g_wtab + ((size_t)lay * TROWS + row) * 256;
    *(float4*)(out + c0) = ws;
    *(float4*)(out + 128 + c0) = wv;
}

// ---------------- 5b. edge apply (dst-sorted, staged indices) -----------------
// Warp per destination; use_hv=0 in layer 0 (h_v is identically zero there).
#define CHUNK 32
__global__ void __launch_bounds__(256) edge_apply_sorted(const int* __restrict__ edges,
                                                         int lay, int use_hv) {
    __shared__ int   sS[8][CHUNK];
    __shared__ float dS[8][CHUNK];
    __shared__ float uS[8][3 * CHUNK];
    int t = blockIdx.x * blockDim.x + threadIdx.x;
    int d = t >> 5;
    if (d >= NB) return;  // warp-uniform exit
    int w = threadIdx.x >> 5;
    int lane = t & 31;
    int c0 = lane * 4;
    const float* wtab = g_wtab + (size_t)lay * TROWS * 256;
    int beg = g_off[d], end = g_off[d + 1];
    float4 as  = make_float4(0, 0, 0, 0);
    float4 av0 = make_float4(0, 0, 0, 0);
    float4 av1 = make_float4(0, 0, 0, 0);
    float4 av2 = make_float4(0, 0, 0, 0);
    for (int base = beg; base < end; base += CHUNK) {
        int cnt = min(CHUNK, end - base);
        if (lane < cnt) {
            int e = g_perm[base + lane];
            sS[w][lane] = edges[e];
            dS[w][lane] = g_d[e];
            uS[w][lane] = g_u[e * 3 + 0];
            uS[w][CHUNK + lane] = g_u[e * 3 + 1];
            uS[w][2 * CHUNK + lane] = g_u[e * 3 + 2];
        }
        __syncwarp();
        if (use_hv) {
            #pragma unroll 2
            for (int j = 0; j < cnt; j++) {
                int s = sS[w][j];
                float dd = dS[w][j];
                float tt = fminf(dd, 5.0f) * (TBINS / 5.0f);
                int idx = min((int)tt, TBINS - 1);
                float f = tt - (float)idx;
                const float* r0 = wtab + (size_t)idx * 256;
                float4 ws = f4lerp(*(const float4*)(r0 + c0),
                                   *(const float4*)(r0 + 256 + c0), f);
                float4 wv = f4lerp(*(const float4*)(r0 + 128 + c0),
                                   *(const float4*)(r0 + 384 + c0), f);
                float4 hs = *(const float4*)(g_hs + (size_t)s * NC + c0);
                as.x += ws.x * hs.x; as.y += ws.y * hs.y;
                as.z += ws.z * hs.z; as.w += ws.w * hs.w;
                float u0 = uS[w][j], u1 = uS[w][CHUNK + j], u2 = uS[w][2 * CHUNK + j];
                const float* hvp = g_hv + (size_t)s * 384;
                float4 hv;
                hv = *(const float4*)(hvp + c0);
                av0.x += wv.x * (hv.x + hs.x * u0); av0.y += wv.y * (hv.y + hs.y * u0);
                av0.z += wv.z * (hv.z + hs.z * u0); av0.w += wv.w * (hv.w + hs.w * u0);
                hv = *(const float4*)(hvp + 128 + c0);
                av1.x += wv.x * (hv.x + hs.x * u1); av1.y += wv.y * (hv.y + hs.y * u1);
                av1.z += wv.z * (hv.z + hs.z * u1); av1.w += wv.w * (hv.w + hs.w * u1);
                hv = *(const float4*)(hvp + 256 + c0);
                av2.x += wv.x * (hv.x + hs.x * u2); av2.y += wv.y * (hv.y + hs.y * u2);
                av2.z += wv.z * (hv.z + hs.z * u2); av2.w += wv.w * (hv.w + hs.w * u2);
            }
        } else {
            // layer 0: h_v == 0, msg_v = wv * hs * u — no g_hv reads
            #pragma unroll 2
            for (int j = 0; j < cnt; j++) {
                int s = sS[w][j];
                float dd = dS[w][j];
                float tt = fminf(dd, 5.0f) * (TBINS / 5.0f);
                int idx = min((int)tt, TBINS - 1);
                float f = tt - (float)idx;
                const float* r0 = wtab + (size_t)idx * 256;
                float4 ws = f4lerp(*(const float4*)(r0 + c0),
                                   *(const float4*)(r0 + 256 + c0), f);
                float4 wv = f4lerp(*(const float4*)(r0 + 128 + c0),
                                   *(const float4*)(r0 + 384 + c0), f);
                float4 hs = *(const float4*)(g_hs + (size_t)s * NC + c0);
                as.x += ws.x * hs.x; as.y += ws.y * hs.y;
                as.z += ws.z * hs.z; as.w += ws.w * hs.w;
                float u0 = uS[w][j], u1 = uS[w][CHUNK + j], u2 = uS[w][2 * CHUNK + j];
                float4 wh;
                wh.x = wv.x * hs.x; wh.y = wv.y * hs.y;
                wh.z = wv.z * hs.z; wh.w = wv.w * hs.w;
                av0.x += wh.x * u0; av0.y += wh.y * u0;
                av0.z += wh.z * u0; av0.w += wh.w * u0;
                av1.x += wh.x * u1; av1.y += wh.y * u1;
                av1.z += wh.z * u1; av1.w += wh.w * u1;
                av2.x += wh.x * u2; av2.y += wh.y * u2;
                av2.z += wh.z * u2; av2.w += wh.w * u2;
            }
        }
        __syncwarp();
    }
    *(float4*)(g_aggs + (size_t)d * NC + c0) = as;
    float* avp = g_aggv + (size_t)d * 384;
    *(float4*)(avp + c0) = av0;
    *(float4*)(avp + 128 + c0) = av1;
    *(float4*)(avp + 256 + c0) = av2;
}

// ---------------- 6. node s-update GEMM --------------------------------------
__global__ void __launch_bounds__(256) gemm_s(const float* __restrict__ Wsl, int l,
                                              float* __restrict__ outB) {
    extern __shared__ float sm[];
    float* W0 = sm;
    float* W1 = sm + 16384;
    float* As = sm + 32768;  // 64*132
    const float* W2 = Wsl + 32768;
    int tid = threadIdx.x;
    for (int i = tid; i < 2 * 16384; i += 256) sm[i] = Wsl[i];
    int m0 = blockIdx.x * 64;
    for (int i = tid; i < 64 * 32; i += 256) {
        int r = i >> 5, kq = (i & 31) * 4;
        float4 v = make_float4(0, 0, 0, 0);
        int m = m0 + r;
        if (m < NB) v = *(const float4*)(g_aggs + (size_t)m * NC + kq);
        *(float4*)(As + r * 132 + kq) = v;
    }
    __syncthreads();
    int tr = (tid >> 4) << 2;
    int tc = (tid & 15) << 3;
    float4 acc0[4] = {}, acc1[4] = {};
    for (int k = 0; k < 128; k++) {
        float4 b00 = *(const float4*)(W0 + k * 128 + tc);
        float4 b01 = *(const float4*)(W0 + k * 128 + tc + 4);
        float4 b10 = *(const float4*)(W1 + k * 128 + tc);
        float4 b11 = *(const float4*)(W1 + k * 128 + tc + 4);
        float4 b20 = __ldg((const float4*)(W2 + k * 128 + tc));
        float4 b21 = __ldg((const float4*)(W2 + k * 128 + tc + 4));
        #pragma unroll
        for (int i = 0; i < 4; i++) {
            float a = As[(tr + i) * 132 + k];
            float a2 = a * a, a3 = a2 * a;
            acc0[i] = f4fma(a, b00, acc0[i]);
            acc0[i] = f4fma(a2, b10, acc0[i]);
            acc0[i] = f4fma(a3, b20, acc0[i]);
            acc1[i] = f4fma(a, b01, acc1[i]);
            acc1[i] = f4fma(a2, b11, acc1[i]);
            acc1[i] = f4fma(a3, b21, acc1[i]);
        }
    }
    #pragma unroll
    for (int i = 0; i < 4; i++) {
        int m = m0 + tr + i;
        if (m >= NB) continue;
        float* hsrow = g_hs + (size_t)m * NC + tc;
        float4 v0 = acc0[i], v1 = acc1[i];
        if (l) {
            v0 = f4add(v0, *(float4*)hsrow);
            v1 = f4add(v1, *(float4*)(hsrow + 4));
        }
        *(float4*)hsrow = v0;
        *(float4*)(hsrow + 4) = v1;
        float* fo = outB + (size_t)m * 1024 + l * 512 + tc;
        *(float4*)fo = v0;
        *(float4*)(fo + 4) = v1;
    }
}

// ---------------- 7. node v-update GEMM --------------------------------------
__global__ void __launch_bounds__(256) gemm_v(const float* __restrict__ Wvl,
                                              const float* __restrict__ wsvl, int l,
                                              float* __restrict__ outB) {
    extern __shared__ float sm[];
    float* Bs = sm;            // 128*128
    float* As = sm + 16384;    // 64*132
    __shared__ float wsvs[128];
    int tid = threadIdx.x;
    for (int i = tid; i < 16384; i += 256) Bs[i] = Wvl[i];
    if (tid < 128) wsvs[tid] = wsvl[tid];
    int m0 = blockIdx.x * 64;
    for (int i = tid; i < 64 * 32; i += 256) {
        int r = i >> 5, kq = (i & 31) * 4;
        float4 v = make_float4(0, 0, 0, 0);
        int m = m0 + r;
        if (m < NB * 3) v = *(const float4*)(g_aggv + (size_t)m * NC + kq);
        *(float4*)(As + r * 132 + kq) = v;
    }
    __syncthreads();
    int tr = (tid >> 4) << 2;
    int tc = (tid & 15) << 3;
    float4 acc0[4] = {}, acc1[4] = {};
    for (int k = 0; k < 128; k++) {
        float4 b0 = *(const float4*)(Bs + k * 128 + tc);
        float4 b1 = *(const float4*)(Bs + k * 128 + tc + 4);
        #pragma unroll
        for (int i = 0; i < 4; i++) {
            float a = As[(tr + i) * 132 + k];
            acc0[i] = f4fma(a, b0, acc0[i]);
            acc1[i] = f4fma(a, b1, acc1[i]);
        }
    }
    #pragma unroll
    for (int i = 0; i < 4; i++) {
        int m = m0 + tr + i;
        if (m >= NB * 3) continue;
        int n = m / 3;
        int x = m - 3 * n;
        float4 av0 = *(float4*)(As + (tr + i) * 132 + tc);
        float4 av1 = *(float4*)(As + (tr + i) * 132 + tc + 4);
        float4 as0 = *(const float4*)(g_aggs + (size_t)n * NC + tc);
        float4 as1 = *(const float4*)(g_aggs + (size_t)n * NC + tc + 4);
        float4 sv0 = *(const float4*)(wsvs + tc);
        float4 sv1 = *(const float4*)(wsvs + tc + 4);
        float4 r0 = acc0[i], r1 = acc1[i];
        r0.x += sv0.x * as0.x * av0.x; r0.y += sv0.y * as0.y * av0.y;
        r0.z += sv0.z * as0.z * av0.z; r0.w += sv0.w * as0.w * av0.w;
        r1.x += sv1.x * as1.x * av1.x; r1.y += sv1.y * as1.y * av1.y;
        r1.z += sv1.z * as1.z * av1.z; r1.w += sv1.w * as1.w * av1.w;
        float* hvrow = g_hv + (size_t)m * NC + tc;
        if (l) {
            r0 = f4add(r0, *(float4*)hvrow);
            r1 = f4add(r1, *(float4*)(hvrow + 4));
        }
        *(float4*)hvrow = r0;
        *(float4*)(hvrow + 4) = r1;
        // feats layout: 128 + c*3 + x
        float* fo = outB + (size_t)n * 1024 + l * 512 + 128 + x;
        fo[(tc + 0) * 3] = r0.x; fo[(tc + 1) * 3] = r0.y;
        fo[(tc + 2) * 3] = r0.z; fo[(tc + 3) * 3] = r0.w;
        fo[(tc + 4) * 3] = r1.x; fo[(tc + 5) * 3] = r1.y;
        fo[(tc + 6) * 3] = r1.z; fo[(tc + 7) * 3] = r1.w;
    }
}

// ---------------- 8. normalize rows + scatter to graphs ----------------------
__global__ void norm_block(float* __restrict__ outB, float* __restrict__ outC,
                           const int* __restrict__ batch_id) {
    int t = blockIdx.x * blockDim.x + threadIdx.x;
    int n = t >> 5;
    if (n >= NB) return;
    int lane = t & 31;
    float* row = outB + (size_t)n * 1024;
    float4 v[8];
    float ss = 0.0f;
    #pragma unroll
    for (int i = 0; i < 8; i++) {
        v[i] = *(float4*)(row + i * 128 + lane * 4);
        ss += v[i].x * v[i].x + v[i].y * v[i].y + v[i].z * v[i].z + v[i].w * v[i].w;
    }
    #pragma unroll
    for (int o = 16; o; o >>= 1) ss += __shfl_xor_sync(0xffffffffu, ss, o);
    float inv = 1.0f / fmaxf(sqrtf(ss), 1e-12f);
    int b = batch_id[n];
    float* grow = outC + (size_t)b * 1024;
    #pragma unroll
    for (int i = 0; i < 8; i++) {
        v[i] = f4scale(v[i], inv);
        *(float4*)(row + i * 128 + lane * 4) = v[i];
        red_add_v4(grow + i * 128 + lane * 4, v[i]);
    }
}

__global__ void norm_g(float* __restrict__ outC) {
    int t = blockIdx.x * blockDim.x + threadIdx.x;
    int n = t >> 5;
    if (n >= NG) return;
    int lane = t & 31;
    float* row = outC + (size_t)n * 1024;
    float4 v[8];
    float ss = 0.0f;
    #pragma unroll
    for (int i = 0; i < 8; i++) {
        v[i] = *(float4*)(row + i * 128 + lane * 4);
        ss += v[i].x * v[i].x + v[i].y * v[i].y + v[i].z * v[i].z + v[i].w * v[i].w;
    }
    #pragma unroll
    for (int o = 16; o; o >>= 1) ss += __shfl_xor_sync(0xffffffffu, ss, o);
    float inv = 1.0f / fmaxf(sqrtf(ss), 1e-12f);
    #pragma unroll
    for (int i = 0; i < 8; i++)
        *(float4*)(row + i * 128 + lane * 4) = f4scale(v[i], inv);
}

// ---------------- launch ------------------------------------------------------
extern "C" void kernel_launch(void* const* d_in, const int* in_sizes, int n_in,
                              void* d_out, int out_size) {
    const float* H       = (const float*)d_in[0];
    const float* Z       = (const float*)d_in[1];
    const float* W_embed = (const float*)d_in[2];
    const float* Wr1     = (const float*)d_in[3];
    const float* br1     = (const float*)d_in[4];
    const float* Wr2     = (const float*)d_in[5];
    const float* Ws      = (const float*)d_in[6];
    const float* Wv      = (const float*)d_in[7];
    const float* wsv     = (const float*)d_in[8];
    const int* block_id  = (const int*)d_in[9];
    const int* batch_id  = (const int*)d_in[10];
    const int* edges     = (const int*)d_in[11];

    float* outA = (float*)d_out;                    // Hb        [20000,128]
    float* outB = outA + (size_t)NB * NC;           // block_repr[20000,1024]
    float* outC = outB + (size_t)NB * 1024;         // graph_repr[512,1024]

    const int BT_SMEM = (1024 + 64 + 16384 + 8 * 64) * 4;           // 71936
    const int GS_SMEM = (2 * 16384 + 64 * 132) * 4;                 // 164864
    const int GV_SMEM = (16384 + 64 * 132) * 4;                     // 99328

    cudaFuncSetAttribute(build_wtab, cudaFuncAttributeMaxDynamicSharedMemorySize, BT_SMEM);
    cudaFuncSetAttribute(gemm_s,     cudaFuncAttributeMaxDynamicSharedMemorySize, GS_SMEM);
    cudaFuncSetAttribute(gemm_v,     cudaFuncAttributeMaxDynamicSharedMemorySize, GV_SMEM);
    cudaFuncSetAttribute(gemm_embed, cudaFuncAttributeMaxDynamicSharedMemorySize, GV_SMEM);

    void *pZb, *pcnt, *pdeg;
    cudaGetSymbolAddress(&pZb, g_Zb);
    cudaGetSymbolAddress(&pcnt, g_cnt);
    cudaGetSymbolAddress(&pdeg, g_deg);

    cudaMemsetAsync(outA, 0, (size_t)NB * NC * 4);
    cudaMemsetAsync(outC, 0, (size_t)NG * 1024 * 4);
    cudaMemsetAsync(pZb, 0, (size_t)NB * 3 * 4);
    cudaMemsetAsync(pcnt, 0, (size_t)NB * 4);
    cudaMemsetAsync(pdeg, 0, (size_t)NB * 4);
    // g_hv memset dropped: layer-0 gemm_v overwrites it fully (l=0 store),
    // and layer-0 edge_apply runs with use_hv=0.

    atom_scatter<<<(NA * 32 + 255) / 256, 256>>>(H, Z, block_id, outA);
    finalize_blocks<<<(NB * 32 + 255) / 256, 256>>>(outA);
    gemm_embed<<<(NB + 63) / 64, 256, GV_SMEM>>>(outA, W_embed);
    edge_geom<<<(NE + 255) / 256, 256>>>(edges);
    scan_offsets<<<1, 256>>>();
    scatter_perm<<<(NE + 255) / 256, 256>>>(edges);
    build_wtab<<<(2 * TROWS + 7) / 8, 256, BT_SMEM>>>(Wr1, br1, Wr2);

    for (int l = 0; l < 2; l++) {
        edge_apply_sorted<<<(NB * 32 + 255) / 256, 256>>>(edges, l, l);
        gemm_s<<<(NB + 63) / 64, 256, GS_SMEM>>>(Ws + (size_t)l * 3 * 16384, l, outB);
        gemm_v<<<(NB * 3 + 63) / 64, 256, GV_SMEM>>>(Wv + (size_t)l * 16384,
                                                     wsv + l * 128, l, outB);
    }

    norm_block<<<(NB * 32 + 255) / 256, 256>>>(outB, outC, batch_id);
    norm_g<<<(NG * 32 + 255) / 256, 256>>>(outC);
}

// round 16
// speedup vs baseline: 1.8997x; 1.0504x over previous
#include <cuda_runtime.h>
#include <cuda_fp16.h>
#include <math.h>
#include <stdint.h>

#define NB 20000
#define NA 80000
#define NE 320000
#define NC 128
#define NG 512
#define TBINS 16384
#define TROWS (TBINS + 1)
#define PI_F 3.14159265358979323846f

// ---------------- scratch (device globals; no allocation allowed) -------------
__device__ float g_Zb[NB * 3];
__device__ float g_cnt[NB];
__device__ float g_hs[NB * NC];            // h_s [n][c]
__device__ float g_hv[NB * 3 * NC];        // h_v [n][x][c]
__device__ float g_aggs[NB * NC];          // agg_s [n][c]
__device__ float g_aggv[NB * 3 * NC];      // agg_v [n][x][c]
__device__ float g_d[NE];
__device__ float g_u[NE * 3];
__device__ __half2 g_wtabh[2 * (size_t)TROWS * 128];  // fp16 table: row=128 half2 [ws|wv]
__device__ int   g_deg[NB];
__device__ int   g_off[NB + 1];
__device__ int   g_cur[NB];
__device__ int   g_perm[NE];

// ---------------- helpers ----------------------------------------------------
__device__ __forceinline__ void red_add_v4(float* addr, float4 v) {
    asm volatile("red.global.add.v4.f32 [%0], {%1,%2,%3,%4};"
                 :: "l"(addr), "f"(v.x), "f"(v.y), "f"(v.z), "f"(v.w)
                 : "memory");
}
__device__ __forceinline__ float4 f4fma(float a, float4 b, float4 c) {
    c.x += a * b.x; c.y += a * b.y; c.z += a * b.z; c.w += a * b.w; return c;
}
__device__ __forceinline__ float4 f4add(float4 a, float4 b) {
    a.x += b.x; a.y += b.y; a.z += b.z; a.w += b.w; return a;
}
__device__ __forceinline__ float4 f4scale(float4 a, float s) {
    a.x *= s; a.y *= s; a.z *= s; a.w *= s; return a;
}
__device__ __forceinline__ float4 f4lerp(float4 a, float4 b, float f) {
    a.x += f * (b.x - a.x); a.y += f * (b.y - a.y);
    a.z += f * (b.z - a.z); a.w += f * (b.w - a.w); return a;
}
__device__ __forceinline__ float4 ld_half4(const __half2* p) {
    uint2 raw = *(const uint2*)p;
    __half2 a = *(__half2*)&raw.x;
    __half2 b = *(__half2*)&raw.y;
    float2 fa = __half22float2(a);
    float2 fb = __half22float2(b);
    return make_float4(fa.x, fa.y, fb.x, fb.y);
}

// ---------------- 1. atom -> block scatter (sums) -----------------------------
__global__ void atom_scatter(const float* __restrict__ H, const float* __restrict__ Z,
                             const int* __restrict__ bid, float* __restrict__ HbSum) {
    int t = blockIdx.x * blockDim.x + threadIdx.x;
    int a = t >> 5;
    if (a >= NA) return;
    int lane = t & 31;
    int b = bid[a];
    float4 v = *(const float4*)(H + (size_t)a * NC + lane * 4);
    red_add_v4(HbSum + (size_t)b * NC + lane * 4, v);
    if (lane < 3) atomicAdd(&g_Zb[b * 3 + lane], Z[a * 3 + lane]);
    if (lane == 0) atomicAdd(&g_cnt[b], 1.0f);
}

// ---------------- 2. finalize means ------------------------------------------
__global__ void finalize_blocks(float* __restrict__ Hb) {
    int t = blockIdx.x * blockDim.x + threadIdx.x;
    int b = t >> 5;
    if (b >= NB) return;
    int lane = t & 31;
    float inv = 1.0f / fmaxf(g_cnt[b], 1.0f);
    float4* p = (float4*)(Hb + (size_t)b * NC + lane * 4);
    *p = f4scale(*p, inv);
    if (lane < 3) g_Zb[b * 3 + lane] *= inv;
}

// ---------------- 3. edge geometry: d, u + degree histogram -------------------
__global__ void edge_geom(const int* __restrict__ edges) {
    int e = blockIdx.x * blockDim.x + threadIdx.x;
    if (e >= NE) return;
    int s = edges[e], d_ = edges[NE + e];
    float rx = g_Zb[d_ * 3 + 0] - g_Zb[s * 3 + 0];
    float ry = g_Zb[d_ * 3 + 1] - g_Zb[s * 3 + 1];
    float rz = g_Zb[d_ * 3 + 2] - g_Zb[s * 3 + 2];
    float d = sqrtf(rx * rx + ry * ry + rz * rz + 1e-12f);
    float invd = 1.0f / d;
    g_d[e] = d;
    g_u[e * 3 + 0] = rx * invd;
    g_u[e * 3 + 1] = ry * invd;
    g_u[e * 3 + 2] = rz * invd;
    if (s != d_) atomicAdd(&g_deg[d_], 1);   // masked edges never enter lists
}

// ---------------- 3b. exclusive scan of degrees (single CTA) ------------------
__global__ void scan_offsets() {
    __shared__ int partial[256];
    const int CH = (NB + 255) / 256;  // 79
    int t = threadIdx.x;
    int base = t * CH;
    int sum = 0;
    for (int i = 0; i < CH; i++) {
        int idx = base + i;
        if (idx < NB) sum += g_deg[idx];
    }
    partial[t] = sum;
    __syncthreads();
    for (int off = 1; off < 256; off <<= 1) {
        int v = 0;
        if (t >= off) v = partial[t - off];
        __syncthreads();
        if (t >= off) partial[t] += v;
        __syncthreads();
    }
    int run = (t == 0) ? 0 : partial[t - 1];
    for (int i = 0; i < CH; i++) {
        int idx = base + i;
        if (idx < NB) {
            g_off[idx] = run;
            g_cur[idx] = run;
            run += g_deg[idx];
        }
    }
    if (t == 255) g_off[NB] = run;
}

// ---------------- 3c. scatter edges into dst-sorted order ---------------------
__global__ void scatter_perm(const int* __restrict__ edges) {
    int e = blockIdx.x * blockDim.x + threadIdx.x;
    if (e >= NE) return;
    int s = edges[e], dst = edges[NE + e];
    if (s == dst) return;
    int pos = atomicAdd(&g_cur[dst], 1);
    g_perm[pos] = e;
}

// ---------------- 4. embed GEMM: h_s = Hb @ W_embed --------------------------
__global__ void __launch_bounds__(256) gemm_embed(const float* __restrict__ A,
                                                  const float* __restrict__ B) {
    extern __shared__ float sm[];
    float* Bs = sm;            // 128*128
    float* As = sm + 16384;    // 64*132
    int tid = threadIdx.x;
    for (int i = tid; i < 16384; i += 256) Bs[i] = B[i];
    int m0 = blockIdx.x * 64;
    for (int i = tid; i < 64 * 32; i += 256) {
        int r = i >> 5, kq = (i & 31) * 4;
        float4 v = make_float4(0, 0, 0, 0);
        int m = m0 + r;
        if (m < NB) v = *(const float4*)(A + (size_t)m * NC + kq);
        *(float4*)(As + r * 132 + kq) = v;
    }
    __syncthreads();
    int tr = (tid >> 4) << 2;
    int tc = (tid & 15) << 3;
    float4 acc0[4] = {}, acc1[4] = {};
    for (int k = 0; k < 128; k++) {
        float4 b0 = *(const float4*)(Bs + k * 128 + tc);
        float4 b1 = *(const float4*)(Bs + k * 128 + tc + 4);
        #pragma unroll
        for (int i = 0; i < 4; i++) {
            float a = As[(tr + i) * 132 + k];
            acc0[i] = f4fma(a, b0, acc0[i]);
            acc1[i] = f4fma(a, b1, acc1[i]);
        }
    }
    #pragma unroll
    for (int i = 0; i < 4; i++) {
        int m = m0 + tr + i;
        if (m >= NB) continue;
        *(float4*)(g_hs + (size_t)m * NC + tc) = acc0[i];
        *(float4*)(g_hs + (size_t)m * NC + tc + 4) = acc1[i];
    }
}

// ---------------- 5a. build w(d) tables for BOTH layers (fp16 output) ---------
__global__ void __launch_bounds__(256) build_wtab(const float* __restrict__ Wr1,
                                                  const float* __restrict__ br1,
                                                  const float* __restrict__ Wr2) {
    extern __shared__ float sm[];
    float* Wr1s = sm;                 // 16*64
    float* br1s = Wr1s + 1024;        // 64
    float* Wr2s = br1s + 64;          // 64*256
    float* hids = Wr2s + 16384;       // 8*64
    int tid = threadIdx.x;
    int warp = tid >> 5, lane = tid & 31;
    int gr = blockIdx.x * 8 + warp;   // global row in [0, 2*TROWS)
    int row, lay;
    if (gr < TROWS) { lay = 0; row = gr; }
    else            { lay = 1; row = gr - TROWS; }
    int cta_lay = (blockIdx.x * 8 < TROWS) ? 0 : 1;
    for (int i = tid; i < 1024; i += 256) Wr1s[i] = Wr1[cta_lay * 1024 + i];
    for (int i = tid; i < 64; i += 256) br1s[i] = br1[cta_lay * 64 + i];
    for (int i = tid; i < 16384; i += 256) Wr2s[i] = Wr2[cta_lay * 16384 + i];
    __syncthreads();
    if (gr >= 2 * TROWS) return;
    bool inS = (lay == cta_lay);
    const float* Wr1p = inS ? Wr1s : (Wr1 + lay * 1024);
    const float* br1p = inS ? br1s : (br1 + lay * 64);
    const float* Wr2p = inS ? Wr2s : (Wr2 + lay * 16384);

    float* hid = hids + warp * 64;
    float d = fmaxf(row * (5.0f / TBINS), 1e-6f);
    float rv = 0.0f;
    if (lane < 16) {
        float x = d * 0.2f;
        float fcut = 0.0f;
        if (x < 1.0f) {
            float x2 = x * x, x5 = x2 * x2 * x;
            fcut = 1.0f - 21.0f * x5 + 35.0f * x5 * x - 15.0f * x5 * x2;
        }
        float pref = 0.6324555320336759f / d * fcut;
        rv = pref * sinf((lane + 1) * (PI_F * 0.2f) * d);
    }
    float h0 = br1p[lane], h1 = br1p[lane + 32];
    #pragma unroll
    for (int k = 0; k < 16; k++) {
        float r = __shfl_sync(0xffffffffu, rv, k);
        h0 += r * Wr1p[k * 64 + lane];
        h1 += r * Wr1p[k * 64 + lane + 32];
    }
    h0 = h0 / (1.0f + __expf(-h0));
    h1 = h1 / (1.0f + __expf(-h1));
    __syncwarp();
    hid[lane] = h0;
    hid[lane + 32] = h1;
    __syncwarp();
    int c0 = lane * 4;
    float4 ws = make_float4(0, 0, 0, 0), wv = make_float4(0, 0, 0, 0);
    #pragma unroll 8
    for (int h = 0; h < 64; h++) {
        float hv = hid[h];
        ws = f4fma(hv, *(const float4*)(Wr2p + h * 256 + c0), ws);
        wv = f4fma(hv, *(const float4*)(Wr2p + h * 256 + 128 + c0), wv);
    }
    __half2* out = g_wtabh + ((size_t)lay * TROWS + row) * 128 + lane * 2;
    out[0] = __floats2half2_rn(ws.x, ws.y);
    out[1] = __floats2half2_rn(ws.z, ws.w);
    out[64] = __floats2half2_rn(wv.x, wv.y);
    out[65] = __floats2half2_rn(wv.z, wv.w);
}

// ---------------- 5b. edge apply (dst-sorted, staged indices, fp16 table) -----
#define CHUNK 32
__global__ void __launch_bounds__(256) edge_apply_sorted(const int* __restrict__ edges,
                                                         int lay, int use_hv) {
    __shared__ int   sS[8][CHUNK];
    __shared__ float dS[8][CHUNK];
    __shared__ float uS[8][3 * CHUNK];
    int t = blockIdx.x * blockDim.x + threadIdx.x;
    int d = t >> 5;
    if (d >= NB) return;  // warp-uniform exit
    int w = threadIdx.x >> 5;
    int lane = t & 31;
    int c0 = lane * 4;
    const __half2* wtab = g_wtabh + (size_t)lay * TROWS * 128 + lane * 2;
    int beg = g_off[d], end = g_off[d + 1];
    float4 as  = make_float4(0, 0, 0, 0);
    float4 av0 = make_float4(0, 0, 0, 0);
    float4 av1 = make_float4(0, 0, 0, 0);
    float4 av2 = make_float4(0, 0, 0, 0);
    for (int base = beg; base < end; base += CHUNK) {
        int cnt = min(CHUNK, end - base);
        if (lane < cnt) {
            int e = g_perm[base + lane];
            sS[w][lane] = edges[e];
            dS[w][lane] = g_d[e];
            uS[w][lane] = g_u[e * 3 + 0];
            uS[w][CHUNK + lane] = g_u[e * 3 + 1];
            uS[w][2 * CHUNK + lane] = g_u[e * 3 + 2];
        }
        __syncwarp();
        if (use_hv) {
            #pragma unroll 2
            for (int j = 0; j < cnt; j++) {
                int s = sS[w][j];
                float dd = dS[w][j];
                float tt = fminf(dd, 5.0f) * (TBINS / 5.0f);
                int idx = min((int)tt, TBINS - 1);
                float f = tt - (float)idx;
                const __half2* r0 = wtab + (size_t)idx * 128;
                float4 ws = f4lerp(ld_half4(r0), ld_half4(r0 + 128), f);
                float4 wv = f4lerp(ld_half4(r0 + 64), ld_half4(r0 + 192), f);
                float4 hs = *(const float4*)(g_hs + (size_t)s * NC + c0);
                as.x += ws.x * hs.x; as.y += ws.y * hs.y;
                as.z += ws.z * hs.z; as.w += ws.w * hs.w;
                float u0 = uS[w][j], u1 = uS[w][CHUNK + j], u2 = uS[w][2 * CHUNK + j];
                const float* hvp = g_hv + (size_t)s * 384;
                float4 hv;
                hv = *(const float4*)(hvp + c0);
                av0.x += wv.x * (hv.x + hs.x * u0); av0.y += wv.y * (hv.y + hs.y * u0);
                av0.z += wv.z * (hv.z + hs.z * u0); av0.w += wv.w * (hv.w + hs.w * u0);
                hv = *(const float4*)(hvp + 128 + c0);
                av1.x += wv.x * (hv.x + hs.x * u1); av1.y += wv.y * (hv.y + hs.y * u1);
                av1.z += wv.z * (hv.z + hs.z * u1); av1.w += wv.w * (hv.w + hs.w * u1);
                hv = *(const float4*)(hvp + 256 + c0);
                av2.x += wv.x * (hv.x + hs.x * u2); av2.y += wv.y * (hv.y + hs.y * u2);
                av2.z += wv.z * (hv.z + hs.z * u2); av2.w += wv.w * (hv.w + hs.w * u2);
            }
        } else {
            // layer 0: h_v == 0, msg_v = wv * hs * u — no g_hv reads
            #pragma unroll 2
            for (int j = 0; j < cnt; j++) {
                int s = sS[w][j];
                float dd = dS[w][j];
                float tt = fminf(dd, 5.0f) * (TBINS / 5.0f);
                int idx = min((int)tt, TBINS - 1);
                float f = tt - (float)idx;
                const __half2* r0 = wtab + (size_t)idx * 128;
                float4 ws = f4lerp(ld_half4(r0), ld_half4(r0 + 128), f);
                float4 wv = f4lerp(ld_half4(r0 + 64), ld_half4(r0 + 192), f);
                float4 hs = *(const float4*)(g_hs + (size_t)s * NC + c0);
                as.x += ws.x * hs.x; as.y += ws.y * hs.y;
                as.z += ws.z * hs.z; as.w += ws.w * hs.w;
                float u0 = uS[w][j], u1 = uS[w][CHUNK + j], u2 = uS[w][2 * CHUNK + j];
                float4 wh;
                wh.x = wv.x * hs.x; wh.y = wv.y * hs.y;
                wh.z = wv.z * hs.z; wh.w = wv.w * hs.w;
                av0.x += wh.x * u0; av0.y += wh.y * u0;
                av0.z += wh.z * u0; av0.w += wh.w * u0;
                av1.x += wh.x * u1; av1.y += wh.y * u1;
                av1.z += wh.z * u1; av1.w += wh.w * u1;
                av2.x += wh.x * u2; av2.y += wh.y * u2;
                av2.z += wh.z * u2; av2.w += wh.w * u2;
            }
        }
        __syncwarp();
    }
    *(float4*)(g_aggs + (size_t)d * NC + c0) = as;
    float* avp = g_aggv + (size_t)d * 384;
    *(float4*)(avp + c0) = av0;
    *(float4*)(avp + 128 + c0) = av1;
    *(float4*)(avp + 256 + c0) = av2;
}

// ---------------- 6. node s-update GEMM --------------------------------------
__global__ void __launch_bounds__(256) gemm_s(const float* __restrict__ Wsl, int l,
                                              float* __restrict__ outB) {
    extern __shared__ float sm[];
    float* W0 = sm;
    float* W1 = sm + 16384;
    float* As = sm + 32768;  // 64*132
    const float* W2 = Wsl + 32768;
    int tid = threadIdx.x;
    for (int i = tid; i < 2 * 16384; i += 256) sm[i] = Wsl[i];
    int m0 = blockIdx.x * 64;
    for (int i = tid; i < 64 * 32; i += 256) {
        int r = i >> 5, kq = (i & 31) * 4;
        float4 v = make_float4(0, 0, 0, 0);
        int m = m0 + r;
        if (m < NB) v = *(const float4*)(g_aggs + (size_t)m * NC + kq);
        *(float4*)(As + r * 132 + kq) = v;
    }
    __syncthreads();
    int tr = (tid >> 4) << 2;
    int tc = (tid & 15) << 3;
    float4 acc0[4] = {}, acc1[4] = {};
    for (int k = 0; k < 128; k++) {
        float4 b00 = *(const float4*)(W0 + k * 128 + tc);
        float4 b01 = *(const float4*)(W0 + k * 128 + tc + 4);
        float4 b10 = *(const float4*)(W1 + k * 128 + tc);
        float4 b11 = *(const float4*)(W1 + k * 128 + tc + 4);
        float4 b20 = __ldg((const float4*)(W2 + k * 128 + tc));
        float4 b21 = __ldg((const float4*)(W2 + k * 128 + tc + 4));
        #pragma unroll
        for (int i = 0; i < 4; i++) {
            float a = As[(tr + i) * 132 + k];
            float a2 = a * a, a3 = a2 * a;
            acc0[i] = f4fma(a, b00, acc0[i]);
            acc0[i] = f4fma(a2, b10, acc0[i]);
            acc0[i] = f4fma(a3, b20, acc0[i]);
            acc1[i] = f4fma(a, b01, acc1[i]);
            acc1[i] = f4fma(a2, b11, acc1[i]);
            acc1[i] = f4fma(a3, b21, acc1[i]);
        }
    }
    #pragma unroll
    for (int i = 0; i < 4; i++) {
        int m = m0 + tr + i;
        if (m >= NB) continue;
        float* hsrow = g_hs + (size_t)m * NC + tc;
        float4 v0 = acc0[i], v1 = acc1[i];
        if (l) {
            v0 = f4add(v0, *(float4*)hsrow);
            v1 = f4add(v1, *(float4*)(hsrow + 4));
        }
        *(float4*)hsrow = v0;
        *(float4*)(hsrow + 4) = v1;
        float* fo = outB + (size_t)m * 1024 + l * 512 + tc;
        *(float4*)fo = v0;
        *(float4*)(fo + 4) = v1;
    }
}

// ---------------- 7. node v-update GEMM --------------------------------------
__global__ void __launch_bounds__(256) gemm_v(const float* __restrict__ Wvl,
                                              const float* __restrict__ wsvl, int l,
                                              float* __restrict__ outB) {
    extern __shared__ float sm[];
    float* Bs = sm;            // 128*128
    float* As = sm + 16384;    // 64*132
    __shared__ float wsvs[128];
    int tid = threadIdx.x;
    for (int i = tid; i < 16384; i += 256) Bs[i] = Wvl[i];
    if (tid < 128) wsvs[tid] = wsvl[tid];
    int m0 = blockIdx.x * 64;
    for (int i = tid; i < 64 * 32; i += 256) {
        int r = i >> 5, kq = (i & 31) * 4;
        float4 v = make_float4(0, 0, 0, 0);
        int m = m0 + r;
        if (m < NB * 3) v = *(const float4*)(g_aggv + (size_t)m * NC + kq);
        *(float4*)(As + r * 132 + kq) = v;
    }
    __syncthreads();
    int tr = (tid >> 4) << 2;
    int tc = (tid & 15) << 3;
    float4 acc0[4] = {}, acc1[4] = {};
    for (int k = 0; k < 128; k++) {
        float4 b0 = *(const float4*)(Bs + k * 128 + tc);
        float4 b1 = *(const float4*)(Bs + k * 128 + tc + 4);
        #pragma unroll
        for (int i = 0; i < 4; i++) {
            float a = As[(tr + i) * 132 + k];
            acc0[i] = f4fma(a, b0, acc0[i]);
            acc1[i] = f4fma(a, b1, acc1[i]);
        }
    }
    #pragma unroll
    for (int i = 0; i < 4; i++) {
        int m = m0 + tr + i;
        if (m >= NB * 3) continue;
        int n = m / 3;
        int x = m - 3 * n;
        float4 av0 = *(float4*)(As + (tr + i) * 132 + tc);
        float4 av1 = *(float4*)(As + (tr + i) * 132 + tc + 4);
        float4 as0 = *(const float4*)(g_aggs + (size_t)n * NC + tc);
        float4 as1 = *(const float4*)(g_aggs + (size_t)n * NC + tc + 4);
        float4 sv0 = *(const float4*)(wsvs + tc);
        float4 sv1 = *(const float4*)(wsvs + tc + 4);
        float4 r0 = acc0[i], r1 = acc1[i];
        r0.x += sv0.x * as0.x * av0.x; r0.y += sv0.y * as0.y * av0.y;
        r0.z += sv0.z * as0.z * av0.z; r0.w += sv0.w * as0.w * av0.w;
        r1.x += sv1.x * as1.x * av1.x; r1.y += sv1.y * as1.y * av1.y;
        r1.z += sv1.z * as1.z * av1.z; r1.w += sv1.w * as1.w * av1.w;
        float* hvrow = g_hv + (size_t)m * NC + tc;
        if (l) {
            r0 = f4add(r0, *(float4*)hvrow);
            r1 = f4add(r1, *(float4*)(hvrow + 4));
        }
        *(float4*)hvrow = r0;
        *(float4*)(hvrow + 4) = r1;
        // feats layout: 128 + c*3 + x
        float* fo = outB + (size_t)n * 1024 + l * 512 + 128 + x;
        fo[(tc + 0) * 3] = r0.x; fo[(tc + 1) * 3] = r0.y;
        fo[(tc + 2) * 3] = r0.z; fo[(tc + 3) * 3] = r0.w;
        fo[(tc + 4) * 3] = r1.x; fo[(tc + 5) * 3] = r1.y;
        fo[(tc + 6) * 3] = r1.z; fo[(tc + 7) * 3] = r1.w;
    }
}

// ---------------- 8. normalize rows + scatter to graphs ----------------------
__global__ void norm_block(float* __restrict__ outB, float* __restrict__ outC,
                           const int* __restrict__ batch_id) {
    int t = blockIdx.x * blockDim.x + threadIdx.x;
    int n = t >> 5;
    if (n >= NB) return;
    int lane = t & 31;
    float* row = outB + (size_t)n * 1024;
    float4 v[8];
    float ss = 0.0f;
    #pragma unroll
    for (int i = 0; i < 8; i++) {
        v[i] = *(float4*)(row + i * 128 + lane * 4);
        ss += v[i].x * v[i].x + v[i].y * v[i].y + v[i].z * v[i].z + v[i].w * v[i].w;
    }
    #pragma unroll
    for (int o = 16; o; o >>= 1) ss += __shfl_xor_sync(0xffffffffu, ss, o);
    float inv = 1.0f / fmaxf(sqrtf(ss), 1e-12f);
    int b = batch_id[n];
    float* grow = outC + (size_t)b * 1024;
    #pragma unroll
    for (int i = 0; i < 8; i++) {
        v[i] = f4scale(v[i], inv);
        *(float4*)(row + i * 128 + lane * 4) = v[i];
        red_add_v4(grow + i * 128 + lane * 4, v[i]);
    }
}

__global__ void norm_g(float* __restrict__ outC) {
    int t = blockIdx.x * blockDim.x + threadIdx.x;
    int n = t >> 5;
    if (n >= NG) return;
    int lane = t & 31;
    float* row = outC + (size_t)n * 1024;
    float4 v[8];
    float ss = 0.0f;
    #pragma unroll
    for (int i = 0; i < 8; i++) {
        v[i] = *(float4*)(row + i * 128 + lane * 4);
        ss += v[i].x * v[i].x + v[i].y * v[i].y + v[i].z * v[i].z + v[i].w * v[i].w;
    }
    #pragma unroll
    for (int o = 16; o; o >>= 1) ss += __shfl_xor_sync(0xffffffffu, ss, o);
    float inv = 1.0f / fmaxf(sqrtf(ss), 1e-12f);
    #pragma unroll
    for (int i = 0; i < 8; i++)
        *(float4*)(row + i * 128 + lane * 4) = f4scale(v[i], inv);
}

// ---------------- launch ------------------------------------------------------
extern "C" void kernel_launch(void* const* d_in, const int* in_sizes, int n_in,
                              void* d_out, int out_size) {
    const float* H       = (const float*)d_in[0];
    const float* Z       = (const float*)d_in[1];
    const float* W_embed = (const float*)d_in[2];
    const float* Wr1     = (const float*)d_in[3];
    const float* br1     = (const float*)d_in[4];
    const float* Wr2     = (const float*)d_in[5];
    const float* Ws      = (const float*)d_in[6];
    const float* Wv      = (const float*)d_in[7];
    const float* wsv     = (const float*)d_in[8];
    const int* block_id  = (const int*)d_in[9];
    const int* batch_id  = (const int*)d_in[10];
    const int* edges     = (const int*)d_in[11];

    float* outA = (float*)d_out;                    // Hb        [20000,128]
    float* outB = outA + (size_t)NB * NC;           // block_repr[20000,1024]
    float* outC = outB + (size_t)NB * 1024;         // graph_repr[512,1024]

    const int BT_SMEM = (1024 + 64 + 16384 + 8 * 64) * 4;           // 71936
    const int GS_SMEM = (2 * 16384 + 64 * 132) * 4;                 // 164864
    const int GV_SMEM = (16384 + 64 * 132) * 4;                     // 99328

    cudaFuncSetAttribute(build_wtab, cudaFuncAttributeMaxDynamicSharedMemorySize, BT_SMEM);
    cudaFuncSetAttribute(gemm_s,     cudaFuncAttributeMaxDynamicSharedMemorySize, GS_SMEM);
    cudaFuncSetAttribute(gemm_v,     cudaFuncAttributeMaxDynamicSharedMemorySize, GV_SMEM);
    cudaFuncSetAttribute(gemm_embed, cudaFuncAttributeMaxDynamicSharedMemorySize, GV_SMEM);

    void *pZb, *pcnt, *pdeg;
    cudaGetSymbolAddress(&pZb, g_Zb);
    cudaGetSymbolAddress(&pcnt, g_cnt);
    cudaGetSymbolAddress(&pdeg, g_deg);

    cudaMemsetAsync(outA, 0, (size_t)NB * NC * 4);
    cudaMemsetAsync(outC, 0, (size_t)NG * 1024 * 4);
    cudaMemsetAsync(pZb, 0, (size_t)NB * 3 * 4);
    cudaMemsetAsync(pcnt, 0, (size_t)NB * 4);
    cudaMemsetAsync(pdeg, 0, (size_t)NB * 4);

    atom_scatter<<<(NA * 32 + 255) / 256, 256>>>(H, Z, block_id, outA);
    finalize_blocks<<<(NB * 32 + 255) / 256, 256>>>(outA);
    gemm_embed<<<(NB + 63) / 64, 256, GV_SMEM>>>(outA, W_embed);
    edge_geom<<<(NE + 255) / 256, 256>>>(edges);
    scan_offsets<<<1, 256>>>();
    scatter_perm<<<(NE + 255) / 256, 256>>>(edges);
    build_wtab<<<(2 * TROWS + 7) / 8, 256, BT_SMEM>>>(Wr1, br1, Wr2);

    for (int l = 0; l < 2; l++) {
        edge_apply_sorted<<<(NB * 32 + 255) / 256, 256>>>(edges, l, l);
        gemm_s<<<(NB + 63) / 64, 256, GS_SMEM>>>(Ws + (size_t)l * 3 * 16384, l, outB);
        gemm_v<<<(NB * 3 + 63) / 64, 256, GV_SMEM>>>(Wv + (size_t)l * 16384,
                                                     wsv + l * 128, l, outB);
    }

    norm_block<<<(NB * 32 + 255) / 256, 256>>>(outB, outC, batch_id);
    norm_g<<<(NG * 32 + 255) / 256, 256>>>(outC);
}

// round 17
// speedup vs baseline: 2.0898x; 1.1001x over previous
#include <cuda_runtime.h>
#include <cuda_fp16.h>
#include <math.h>
#include <stdint.h>

#define NB 20000
#define NA 80000
#define NE 320000
#define NC 128
#define NG 512
#define TBINS 16384
#define TROWS (TBINS + 1)
#define PI_F 3.14159265358979323846f

// ---------------- scratch (device globals; no allocation allowed) -------------
__device__ float g_Zb[NB * 3];
__device__ float g_cnt[NB];
__device__ float g_hs[NB * NC];            // h_s [n][c]
__device__ float g_hv[NB * 3 * NC];        // h_v [n][x][c]
__device__ float g_aggs[NB * NC];          // agg_s [n][c]
__device__ float g_aggv[NB * 3 * NC];      // agg_v [n][x][c]
__device__ float g_d[NE];
__device__ float g_u[NE * 3];
__device__ __half2 g_wtabh[2 * (size_t)TROWS * 128];  // fp16 table rows [ws|wv]
__device__ int   g_deg[NB];
__device__ int   g_off[NB + 1];
__device__ int   g_cur[NB];
__device__ int   g_perm[NE];

// ---------------- helpers ----------------------------------------------------
__device__ __forceinline__ void red_add_v4(float* addr, float4 v) {
    asm volatile("red.global.add.v4.f32 [%0], {%1,%2,%3,%4};"
                 :: "l"(addr), "f"(v.x), "f"(v.y), "f"(v.z), "f"(v.w)
                 : "memory");
}
__device__ __forceinline__ float4 f4fma(float a, float4 b, float4 c) {
    c.x += a * b.x; c.y += a * b.y; c.z += a * b.z; c.w += a * b.w; return c;
}
__device__ __forceinline__ float4 f4add(float4 a, float4 b) {
    a.x += b.x; a.y += b.y; a.z += b.z; a.w += b.w; return a;
}
__device__ __forceinline__ float4 f4scale(float4 a, float s) {
    a.x *= s; a.y *= s; a.z *= s; a.w *= s; return a;
}
__device__ __forceinline__ float4 f4lerp(float4 a, float4 b, float f) {
    a.x += f * (b.x - a.x); a.y += f * (b.y - a.y);
    a.z += f * (b.z - a.z); a.w += f * (b.w - a.w); return a;
}
__device__ __forceinline__ float4 ld_half4(const __half2* p) {
    uint2 raw = *(const uint2*)p;
    __half2 a = *(__half2*)&raw.x;
    __half2 b = *(__half2*)&raw.y;
    float2 fa = __half22float2(a);
    float2 fb = __half22float2(b);
    return make_float4(fa.x, fa.y, fb.x, fb.y);
}

// ---------------- 1. atom -> block scatter (sums) -----------------------------
__global__ void atom_scatter(const float* __restrict__ H, const float* __restrict__ Z,
                             const int* __restrict__ bid, float* __restrict__ HbSum) {
    int t = blockIdx.x * blockDim.x + threadIdx.x;
    int a = t >> 5;
    if (a >= NA) return;
    int lane = t & 31;
    int b = bid[a];
    float4 v = *(const float4*)(H + (size_t)a * NC + lane * 4);
    red_add_v4(HbSum + (size_t)b * NC + lane * 4, v);
    if (lane < 3) atomicAdd(&g_Zb[b * 3 + lane], Z[a * 3 + lane]);
    if (lane == 0) atomicAdd(&g_cnt[b], 1.0f);
}

// ---------------- 2. finalize means ------------------------------------------
__global__ void finalize_blocks(float* __restrict__ Hb) {
    int t = blockIdx.x * blockDim.x + threadIdx.x;
    int b = t >> 5;
    if (b >= NB) return;
    int lane = t & 31;
    float inv = 1.0f / fmaxf(g_cnt[b], 1.0f);
    float4* p = (float4*)(Hb + (size_t)b * NC + lane * 4);
    *p = f4scale(*p, inv);
    if (lane < 3) g_Zb[b * 3 + lane] *= inv;
}

// ---------------- 3. edge geometry: d, u + degree histogram -------------------
__global__ void edge_geom(const int* __restrict__ edges) {
    int e = blockIdx.x * blockDim.x + threadIdx.x;
    if (e >= NE) return;
    int s = edges[e], d_ = edges[NE + e];
    float rx = g_Zb[d_ * 3 + 0] - g_Zb[s * 3 + 0];
    float ry = g_Zb[d_ * 3 + 1] - g_Zb[s * 3 + 1];
    float rz = g_Zb[d_ * 3 + 2] - g_Zb[s * 3 + 2];
    float d = sqrtf(rx * rx + ry * ry + rz * rz + 1e-12f);
    float invd = 1.0f / d;
    g_d[e] = d;
    g_u[e * 3 + 0] = rx * invd;
    g_u[e * 3 + 1] = ry * invd;
    g_u[e * 3 + 2] = rz * invd;
    if (s != d_) atomicAdd(&g_deg[d_], 1);
}

// ---------------- 3b. exclusive scan of degrees (single CTA) ------------------
__global__ void scan_offsets() {
    __shared__ int partial[256];
    const int CH = (NB + 255) / 256;
    int t = threadIdx.x;
    int base = t * CH;
    int sum = 0;
    for (int i = 0; i < CH; i++) {
        int idx = base + i;
        if (idx < NB) sum += g_deg[idx];
    }
    partial[t] = sum;
    __syncthreads();
    for (int off = 1; off < 256; off <<= 1) {
        int v = 0;
        if (t >= off) v = partial[t - off];
        __syncthreads();
        if (t >= off) partial[t] += v;
        __syncthreads();
    }
    int run = (t == 0) ? 0 : partial[t - 1];
    for (int i = 0; i < CH; i++) {
        int idx = base + i;
        if (idx < NB) {
            g_off[idx] = run;
            g_cur[idx] = run;
            run += g_deg[idx];
        }
    }
    if (t == 255) g_off[NB] = run;
}

// ---------------- 3c. scatter edges into dst-sorted order ---------------------
__global__ void scatter_perm(const int* __restrict__ edges) {
    int e = blockIdx.x * blockDim.x + threadIdx.x;
    if (e >= NE) return;
    int s = edges[e], dst = edges[NE + e];
    if (s == dst) return;
    int pos = atomicAdd(&g_cur[dst], 1);
    g_perm[pos] = e;
}

// ---------------- 4. embed GEMM: h_s = Hb @ W_embed --------------------------
__global__ void __launch_bounds__(256) gemm_embed(const float* __restrict__ A,
                                                  const float* __restrict__ B) {
    extern __shared__ float sm[];
    float* Bs = sm;            // 128*128
    float* As = sm + 16384;    // 64*132
    int tid = threadIdx.x;
    for (int i = tid; i < 16384; i += 256) Bs[i] = B[i];
    int m0 = blockIdx.x * 64;
    for (int i = tid; i < 64 * 32; i += 256) {
        int r = i >> 5, kq = (i & 31) * 4;
        float4 v = make_float4(0, 0, 0, 0);
        int m = m0 + r;
        if (m < NB) v = *(const float4*)(A + (size_t)m * NC + kq);
        *(float4*)(As + r * 132 + kq) = v;
    }
    __syncthreads();
    int tr = (tid >> 4) << 2;
    int tc = (tid & 15) << 3;
    float4 acc0[4] = {}, acc1[4] = {};
    for (int k = 0; k < 128; k++) {
        float4 b0 = *(const float4*)(Bs + k * 128 + tc);
        float4 b1 = *(const float4*)(Bs + k * 128 + tc + 4);
        #pragma unroll
        for (int i = 0; i < 4; i++) {
            float a = As[(tr + i) * 132 + k];
            acc0[i] = f4fma(a, b0, acc0[i]);
            acc1[i] = f4fma(a, b1, acc1[i]);
        }
    }
    #pragma unroll
    for (int i = 0; i < 4; i++) {
        int m = m0 + tr + i;
        if (m >= NB) continue;
        *(float4*)(g_hs + (size_t)m * NC + tc) = acc0[i];
        *(float4*)(g_hs + (size_t)m * NC + tc + 4) = acc1[i];
    }
}

// ---------------- 5a. build w(d) tables, 4 rows per warp ----------------------
// SMEM Wr2 sweep amortized over 4 rows (4x less SMEM traffic). Batches that
// cross the layer boundary (or tail) fall back to per-row global reads.
__global__ void __launch_bounds__(256) build_wtab(const float* __restrict__ Wr1,
                                                  const float* __restrict__ br1,
                                                  const float* __restrict__ Wr2) {
    extern __shared__ float sm[];
    float* Wr1s = sm;                 // 16*64
    float* br1s = Wr1s + 1024;        // 64
    float* Wr2s = br1s + 64;          // 64*256
    float* hids = Wr2s + 16384;       // 8 warps * 4 rows * 64
    int tid = threadIdx.x;
    int warp = tid >> 5, lane = tid & 31;
    int cta_lay = (blockIdx.x * 32 < TROWS) ? 0 : 1;
    for (int i = tid; i < 1024; i += 256) Wr1s[i] = Wr1[cta_lay * 1024 + i];
    for (int i = tid; i < 64; i += 256) br1s[i] = br1[cta_lay * 64 + i];
    for (int i = tid; i < 16384; i += 256) Wr2s[i] = Wr2[cta_lay * 16384 + i];
    __syncthreads();

    int gr0 = (blockIdx.x * 8 + warp) * 4;
    float* hid = hids + warp * 256;
    int lays[4], rows[4];
    bool uniform = true;
    #pragma unroll
    for (int r = 0; r < 4; r++) {
        int gr = gr0 + r;
        if (gr >= 2 * TROWS) { lays[r] = -1; uniform = false; continue; }
        lays[r] = (gr < TROWS) ? 0 : 1;
        rows[r] = (gr < TROWS) ? gr : gr - TROWS;
        if (lays[r] != cta_lay) uniform = false;
    }
    // Phase A: hidden for each valid row
    #pragma unroll
    for (int r = 0; r < 4; r++) {
        if (lays[r] < 0) continue;
        bool inS = (lays[r] == cta_lay);
        const float* Wr1p = inS ? Wr1s : (Wr1 + lays[r] * 1024);
        const float* br1p = inS ? br1s : (br1 + lays[r] * 64);
        float d = fmaxf(rows[r] * (5.0f / TBINS), 1e-6f);
        float rv = 0.0f;
        if (lane < 16) {
            float x = d * 0.2f;
            float fcut = 0.0f;
            if (x < 1.0f) {
                float x2 = x * x, x5 = x2 * x2 * x;
                fcut = 1.0f - 21.0f * x5 + 35.0f * x5 * x - 15.0f * x5 * x2;
            }
            float pref = 0.6324555320336759f / d * fcut;
            rv = pref * sinf((lane + 1) * (PI_F * 0.2f) * d);
        }
        float h0 = br1p[lane], h1 = br1p[lane + 32];
        #pragma unroll
        for (int k = 0; k < 16; k++) {
            float rr = __shfl_sync(0xffffffffu, rv, k);
            h0 += rr * Wr1p[k * 64 + lane];
            h1 += rr * Wr1p[k * 64 + lane + 32];
        }
        h0 = h0 / (1.0f + __expf(-h0));
        h1 = h1 / (1.0f + __expf(-h1));
        hid[r * 64 + lane] = h0;
        hid[r * 64 + 32 + lane] = h1;
    }
    __syncwarp();
    int c0 = lane * 4;
    if (uniform) {
        float4 ws[4], wv[4];
        #pragma unroll
        for (int r = 0; r < 4; r++) {
            ws[r] = make_float4(0, 0, 0, 0);
            wv[r] = make_float4(0, 0, 0, 0);
        }
        #pragma unroll 4
        for (int h = 0; h < 64; h++) {
            float4 a = *(const float4*)(Wr2s + h * 256 + c0);
            float4 b = *(const float4*)(Wr2s + h * 256 + 128 + c0);
            #pragma unroll
            for (int r = 0; r < 4; r++) {
                float hv = hid[r * 64 + h];
                ws[r] = f4fma(hv, a, ws[r]);
                wv[r] = f4fma(hv, b, wv[r]);
            }
        }
        #pragma unroll
        for (int r = 0; r < 4; r++) {
            __half2* out = g_wtabh + ((size_t)lays[r] * TROWS + rows[r]) * 128 + lane * 2;
            out[0] = __floats2half2_rn(ws[r].x, ws[r].y);
            out[1] = __floats2half2_rn(ws[r].z, ws[r].w);
            out[64] = __floats2half2_rn(wv[r].x, wv[r].y);
            out[65] = __floats2half2_rn(wv[r].z, wv[r].w);
        }
    } else {
        for (int r = 0; r < 4; r++) {
            if (lays[r] < 0) continue;
            const float* Wr2p = (lays[r] == cta_lay) ? Wr2s : (Wr2 + lays[r] * 16384);
            float4 ws = make_float4(0, 0, 0, 0), wv = make_float4(0, 0, 0, 0);
            for (int h = 0; h < 64; h++) {
                float hv = hid[r * 64 + h];
                ws = f4fma(hv, *(const float4*)(Wr2p + h * 256 + c0), ws);
                wv = f4fma(hv, *(const float4*)(Wr2p + h * 256 + 128 + c0), wv);
            }
            __half2* out = g_wtabh + ((size_t)lays[r] * TROWS + rows[r]) * 128 + lane * 2;
            out[0] = __floats2half2_rn(ws.x, ws.y);
            out[1] = __floats2half2_rn(ws.z, ws.w);
            out[64] = __floats2half2_rn(wv.x, wv.y);
            out[65] = __floats2half2_rn(wv.z, wv.w);
        }
    }
}

// ---------------- 5b. edge apply (dst-sorted, staged indices, fp16 table) -----
#define CHUNK 32
__global__ void __launch_bounds__(256) edge_apply_sorted(const int* __restrict__ edges,
                                                         int lay, int use_hv) {
    __shared__ int   sS[8][CHUNK];
    __shared__ float dS[8][CHUNK];
    __shared__ float uS[8][3 * CHUNK];
    int t = blockIdx.x * blockDim.x + threadIdx.x;
    int d = t >> 5;
    if (d >= NB) return;
    int w = threadIdx.x >> 5;
    int lane = t & 31;
    int c0 = lane * 4;
    const __half2* wtab = g_wtabh + (size_t)lay * TROWS * 128 + lane * 2;
    int beg = g_off[d], end = g_off[d + 1];
    float4 as  = make_float4(0, 0, 0, 0);
    float4 av0 = make_float4(0, 0, 0, 0);
    float4 av1 = make_float4(0, 0, 0, 0);
    float4 av2 = make_float4(0, 0, 0, 0);
    for (int base = beg; base < end; base += CHUNK) {
        int cnt = min(CHUNK, end - base);
        if (lane < cnt) {
            int e = g_perm[base + lane];
            sS[w][lane] = edges[e];
            dS[w][lane] = g_d[e];
            uS[w][lane] = g_u[e * 3 + 0];
            uS[w][CHUNK + lane] = g_u[e * 3 + 1];
            uS[w][2 * CHUNK + lane] = g_u[e * 3 + 2];
        }
        __syncwarp();
        if (use_hv) {
            #pragma unroll 2
            for (int j = 0; j < cnt; j++) {
                int s = sS[w][j];
                float dd = dS[w][j];
                float tt = fminf(dd, 5.0f) * (TBINS / 5.0f);
                int idx = min((int)tt, TBINS - 1);
                float f = tt - (float)idx;
                const __half2* r0 = wtab + (size_t)idx * 128;
                float4 ws = f4lerp(ld_half4(r0), ld_half4(r0 + 128), f);
                float4 wv = f4lerp(ld_half4(r0 + 64), ld_half4(r0 + 192), f);
                float4 hs = *(const float4*)(g_hs + (size_t)s * NC + c0);
                as.x += ws.x * hs.x; as.y += ws.y * hs.y;
                as.z += ws.z * hs.z; as.w += ws.w * hs.w;
                float u0 = uS[w][j], u1 = uS[w][CHUNK + j], u2 = uS[w][2 * CHUNK + j];
                const float* hvp = g_hv + (size_t)s * 384;
                float4 hv;
                hv = *(const float4*)(hvp + c0);
                av0.x += wv.x * (hv.x + hs.x * u0); av0.y += wv.y * (hv.y + hs.y * u0);
                av0.z += wv.z * (hv.z + hs.z * u0); av0.w += wv.w * (hv.w + hs.w * u0);
                hv = *(const float4*)(hvp + 128 + c0);
                av1.x += wv.x * (hv.x + hs.x * u1); av1.y += wv.y * (hv.y + hs.y * u1);
                av1.z += wv.z * (hv.z + hs.z * u1); av1.w += wv.w * (hv.w + hs.w * u1);
                hv = *(const float4*)(hvp + 256 + c0);
                av2.x += wv.x * (hv.x + hs.x * u2); av2.y += wv.y * (hv.y + hs.y * u2);
                av2.z += wv.z * (hv.z + hs.z * u2); av2.w += wv.w * (hv.w + hs.w * u2);
            }
        } else {
            #pragma unroll 2
            for (int j = 0; j < cnt; j++) {
                int s = sS[w][j];
                float dd = dS[w][j];
                float tt = fminf(dd, 5.0f) * (TBINS / 5.0f);
                int idx = min((int)tt, TBINS - 1);
                float f = tt - (float)idx;
                const __half2* r0 = wtab + (size_t)idx * 128;
                float4 ws = f4lerp(ld_half4(r0), ld_half4(r0 + 128), f);
                float4 wv = f4lerp(ld_half4(r0 + 64), ld_half4(r0 + 192), f);
                float4 hs = *(const float4*)(g_hs + (size_t)s * NC + c0);
                as.x += ws.x * hs.x; as.y += ws.y * hs.y;
                as.z += ws.z * hs.z; as.w += ws.w * hs.w;
                float u0 = uS[w][j], u1 = uS[w][CHUNK + j], u2 = uS[w][2 * CHUNK + j];
                float4 wh;
                wh.x = wv.x * hs.x; wh.y = wv.y * hs.y;
                wh.z = wv.z * hs.z; wh.w = wv.w * hs.w;
                av0.x += wh.x * u0; av0.y += wh.y * u0;
                av0.z += wh.z * u0; av0.w += wh.w * u0;
                av1.x += wh.x * u1; av1.y += wh.y * u1;
                av1.z += wh.z * u1; av1.w += wh.w * u1;
                av2.x += wh.x * u2; av2.y += wh.y * u2;
                av2.z += wh.z * u2; av2.w += wh.w * u2;
            }
        }
        __syncwarp();
    }
    *(float4*)(g_aggs + (size_t)d * NC + c0) = as;
    float* avp = g_aggv + (size_t)d * 384;
    *(float4*)(avp + c0) = av0;
    *(float4*)(avp + 128 + c0) = av1;
    *(float4*)(avp + 256 + c0) = av2;
}

// ---------------- 6. node s-update GEMM --------------------------------------
__global__ void __launch_bounds__(256) gemm_s(const float* __restrict__ Wsl, int l,
                                              float* __restrict__ outB) {
    extern __shared__ float sm[];
    float* W0 = sm;
    float* W1 = sm + 16384;
    float* As = sm + 32768;  // 64*132
    const float* W2 = Wsl + 32768;
    int tid = threadIdx.x;
    for (int i = tid; i < 2 * 16384; i += 256) sm[i] = Wsl[i];
    int m0 = blockIdx.x * 64;
    for (int i = tid; i < 64 * 32; i += 256) {
        int r = i >> 5, kq = (i & 31) * 4;
        float4 v = make_float4(0, 0, 0, 0);
        int m = m0 + r;
        if (m < NB) v = *(const float4*)(g_aggs + (size_t)m * NC + kq);
        *(float4*)(As + r * 132 + kq) = v;
    }
    __syncthreads();
    int tr = (tid >> 4) << 2;
    int tc = (tid & 15) << 3;
    float4 acc0[4] = {}, acc1[4] = {};
    for (int k = 0; k < 128; k++) {
        float4 b00 = *(const float4*)(W0 + k * 128 + tc);
        float4 b01 = *(const float4*)(W0 + k * 128 + tc + 4);
        float4 b10 = *(const float4*)(W1 + k * 128 + tc);
        float4 b11 = *(const float4*)(W1 + k * 128 + tc + 4);
        float4 b20 = __ldg((const float4*)(W2 + k * 128 + tc));
        float4 b21 = __ldg((const float4*)(W2 + k * 128 + tc + 4));
        #pragma unroll
        for (int i = 0; i < 4; i++) {
            float a = As[(tr + i) * 132 + k];
            float a2 = a * a, a3 = a2 * a;
            acc0[i] = f4fma(a, b00, acc0[i]);
            acc0[i] = f4fma(a2, b10, acc0[i]);
            acc0[i] = f4fma(a3, b20, acc0[i]);
            acc1[i] = f4fma(a, b01, acc1[i]);
            acc1[i] = f4fma(a2, b11, acc1[i]);
            acc1[i] = f4fma(a3, b21, acc1[i]);
        }
    }
    #pragma unroll
    for (int i = 0; i < 4; i++) {
        int m = m0 + tr + i;
        if (m >= NB) continue;
        float* hsrow = g_hs + (size_t)m * NC + tc;
        float4 v0 = acc0[i], v1 = acc1[i];
        if (l) {
            v0 = f4add(v0, *(float4*)hsrow);
            v1 = f4add(v1, *(float4*)(hsrow + 4));
        }
        *(float4*)hsrow = v0;
        *(float4*)(hsrow + 4) = v1;
        float* fo = outB + (size_t)m * 1024 + l * 512 + tc;
        *(float4*)fo = v0;
        *(float4*)(fo + 4) = v1;
    }
}

// ---------------- 7. node v-update GEMM (h_v only; feats via feats_v) ---------
__global__ void __launch_bounds__(256) gemm_v(const float* __restrict__ Wvl,
                                              const float* __restrict__ wsvl, int l) {
    extern __shared__ float sm[];
    float* Bs = sm;            // 128*128
    float* As = sm + 16384;    // 64*132
    __shared__ float wsvs[128];
    int tid = threadIdx.x;
    for (int i = tid; i < 16384; i += 256) Bs[i] = Wvl[i];
    if (tid < 128) wsvs[tid] = wsvl[tid];
    int m0 = blockIdx.x * 64;
    for (int i = tid; i < 64 * 32; i += 256) {
        int r = i >> 5, kq = (i & 31) * 4;
        float4 v = make_float4(0, 0, 0, 0);
        int m = m0 + r;
        if (m < NB * 3) v = *(const float4*)(g_aggv + (size_t)m * NC + kq);
        *(float4*)(As + r * 132 + kq) = v;
    }
    __syncthreads();
    int tr = (tid >> 4) << 2;
    int tc = (tid & 15) << 3;
    float4 acc0[4] = {}, acc1[4] = {};
    for (int k = 0; k < 128; k++) {
        float4 b0 = *(const float4*)(Bs + k * 128 + tc);
        float4 b1 = *(const float4*)(Bs + k * 128 + tc + 4);
        #pragma unroll
        for (int i = 0; i < 4; i++) {
            float a = As[(tr + i) * 132 + k];
            acc0[i] = f4fma(a, b0, acc0[i]);
            acc1[i] = f4fma(a, b1, acc1[i]);
        }
    }
    #pragma unroll
    for (int i = 0; i < 4; i++) {
        int m = m0 + tr + i;
        if (m >= NB * 3) continue;
        int n = m / 3;
        float4 av0 = *(float4*)(As + (tr + i) * 132 + tc);
        float4 av1 = *(float4*)(As + (tr + i) * 132 + tc + 4);
        float4 as0 = *(const float4*)(g_aggs + (size_t)n * NC + tc);
        float4 as1 = *(const float4*)(g_aggs + (size_t)n * NC + tc + 4);
        float4 sv0 = *(const float4*)(wsvs + tc);
        float4 sv1 = *(const float4*)(wsvs + tc + 4);
        float4 r0 = acc0[i], r1 = acc1[i];
        r0.x += sv0.x * as0.x * av0.x; r0.y += sv0.y * as0.y * av0.y;
        r0.z += sv0.z * as0.z * av0.z; r0.w += sv0.w * as0.w * av0.w;
        r1.x += sv1.x * as1.x * av1.x; r1.y += sv1.y * as1.y * av1.y;
        r1.z += sv1.z * as1.z * av1.z; r1.w += sv1.w * as1.w * av1.w;
        float* hvrow = g_hv + (size_t)m * NC + tc;
        if (l) {
            r0 = f4add(r0, *(float4*)hvrow);
            r1 = f4add(r1, *(float4*)(hvrow + 4));
        }
        *(float4*)hvrow = r0;
        *(float4*)(hvrow + 4) = r1;
    }
}

// ---------------- 7b. feats_v: coalesced transpose write of v-features --------
// warp per block-row: read h_v [x][c], SMEM transpose to [c*3+x], write 384
// consecutive floats into outB.
__global__ void __launch_bounds__(256) feats_v(float* __restrict__ outB, int l) {
    __shared__ float smt[8][384];
    int t = blockIdx.x * blockDim.x + threadIdx.x;
    int n = t >> 5;
    if (n >= NB) return;
    int w = threadIdx.x >> 5;
    int lane = t & 31;
    const float* hvp = g_hv + (size_t)n * 384;
    float* s = smt[w];
    #pragma unroll
    for (int x = 0; x < 3; x++) {
        float4 v = *(const float4*)(hvp + x * 128 + lane * 4);
        int c = lane * 4;
        s[(c + 0) * 3 + x] = v.x;
        s[(c + 1) * 3 + x] = v.y;
        s[(c + 2) * 3 + x] = v.z;
        s[(c + 3) * 3 + x] = v.w;
    }
    __syncwarp();
    float* fo = outB + (size_t)n * 1024 + l * 512 + 128;
    #pragma unroll
    for (int i = 0; i < 3; i++) {
        int q = lane * 3 + i;
        *(float4*)(fo + q * 4) = *(float4*)(s + q * 4);
    }
}

// ---------------- 8. normalize rows + scatter to graphs ----------------------
__global__ void norm_block(float* __restrict__ outB, float* __restrict__ outC,
                           const int* __restrict__ batch_id) {
    int t = blockIdx.x * blockDim.x + threadIdx.x;
    int n = t >> 5;
    if (n >= NB) return;
    int lane = t & 31;
    float* row = outB + (size_t)n * 1024;
    float4 v[8];
    float ss = 0.0f;
    #pragma unroll
    for (int i = 0; i < 8; i++) {
        v[i] = *(float4*)(row + i * 128 + lane * 4);
        ss += v[i].x * v[i].x + v[i].y * v[i].y + v[i].z * v[i].z + v[i].w * v[i].w;
    }
    #pragma unroll
    for (int o = 16; o; o >>= 1) ss += __shfl_xor_sync(0xffffffffu, ss, o);
    float inv = 1.0f / fmaxf(sqrtf(ss), 1e-12f);
    int b = batch_id[n];
    float* grow = outC + (size_t)b * 1024;
    #pragma unroll
    for (int i = 0; i < 8; i++) {
        v[i] = f4scale(v[i], inv);
        *(float4*)(row + i * 128 + lane * 4) = v[i];
        red_add_v4(grow + i * 128 + lane * 4, v[i]);
    }
}

__global__ void norm_g(float* __restrict__ outC) {
    int t = blockIdx.x * blockDim.x + threadIdx.x;
    int n = t >> 5;
    if (n >= NG) return;
    int lane = t & 31;
    float* row = outC + (size_t)n * 1024;
    float4 v[8];
    float ss = 0.0f;
    #pragma unroll
    for (int i = 0; i < 8; i++) {
        v[i] = *(float4*)(row + i * 128 + lane * 4);
        ss += v[i].x * v[i].x + v[i].y * v[i].y + v[i].z * v[i].z + v[i].w * v[i].w;
    }
    #pragma unroll
    for (int o = 16; o; o >>= 1) ss += __shfl_xor_sync(0xffffffffu, ss, o);
    float inv = 1.0f / fmaxf(sqrtf(ss), 1e-12f);
    #pragma unroll
    for (int i = 0; i < 8; i++)
        *(float4*)(row + i * 128 + lane * 4) = f4scale(v[i], inv);
}

// ---------------- launch ------------------------------------------------------
extern "C" void kernel_launch(void* const* d_in, const int* in_sizes, int n_in,
                              void* d_out, int out_size) {
    const float* H       = (const float*)d_in[0];
    const float* Z       = (const float*)d_in[1];
    const float* W_embed = (const float*)d_in[2];
    const float* Wr1     = (const float*)d_in[3];
    const float* br1     = (const float*)d_in[4];
    const float* Wr2     = (const float*)d_in[5];
    const float* Ws      = (const float*)d_in[6];
    const float* Wv      = (const float*)d_in[7];
    const float* wsv     = (const float*)d_in[8];
    const int* block_id  = (const int*)d_in[9];
    const int* batch_id  = (const int*)d_in[10];
    const int* edges     = (const int*)d_in[11];

    float* outA = (float*)d_out;                    // Hb        [20000,128]
    float* outB = outA + (size_t)NB * NC;           // block_repr[20000,1024]
    float* outC = outB + (size_t)NB * 1024;         // graph_repr[512,1024]

    const int BT_SMEM = (1024 + 64 + 16384 + 8 * 256) * 4;          // 78080
    const int GS_SMEM = (2 * 16384 + 64 * 132) * 4;                 // 164864
    const int GV_SMEM = (16384 + 64 * 132) * 4;                     // 99328

    cudaFuncSetAttribute(build_wtab, cudaFuncAttributeMaxDynamicSharedMemorySize, BT_SMEM);
    cudaFuncSetAttribute(gemm_s,     cudaFuncAttributeMaxDynamicSharedMemorySize, GS_SMEM);
    cudaFuncSetAttribute(gemm_v,     cudaFuncAttributeMaxDynamicSharedMemorySize, GV_SMEM);
    cudaFuncSetAttribute(gemm_embed, cudaFuncAttributeMaxDynamicSharedMemorySize, GV_SMEM);

    void *pZb, *pcnt, *pdeg;
    cudaGetSymbolAddress(&pZb, g_Zb);
    cudaGetSymbolAddress(&pcnt, g_cnt);
    cudaGetSymbolAddress(&pdeg, g_deg);

    cudaMemsetAsync(outA, 0, (size_t)NB * NC * 4);
    cudaMemsetAsync(outC, 0, (size_t)NG * 1024 * 4);
    cudaMemsetAsync(pZb, 0, (size_t)NB * 3 * 4);
    cudaMemsetAsync(pcnt, 0, (size_t)NB * 4);
    cudaMemsetAsync(pdeg, 0, (size_t)NB * 4);

    atom_scatter<<<(NA * 32 + 255) / 256, 256>>>(H, Z, block_id, outA);
    finalize_blocks<<<(NB * 32 + 255) / 256, 256>>>(outA);
    gemm_embed<<<(NB + 63) / 64, 256, GV_SMEM>>>(outA, W_embed);
    edge_geom<<<(NE + 255) / 256, 256>>>(edges);
    scan_offsets<<<1, 256>>>();
    scatter_perm<<<(NE + 255) / 256, 256>>>(edges);
    build_wtab<<<(2 * TROWS + 31) / 32, 256, BT_SMEM>>>(Wr1, br1, Wr2);

    for (int l = 0; l < 2; l++) {
        edge_apply_sorted<<<(NB * 32 + 255) / 256, 256>>>(edges, l, l);
        gemm_s<<<(NB + 63) / 64, 256, GS_SMEM>>>(Ws + (size_t)l * 3 * 16384, l, outB);
        gemm_v<<<(NB * 3 + 63) / 64, 256, GV_SMEM>>>(Wv + (size_t)l * 16384,
                                                     wsv + l * 128, l);
        feats_v<<<(NB * 32 + 255) / 256, 256>>>(outB, l);
    }

    norm_block<<<(NB * 32 + 255) / 256, 256>>>(outB, outC, batch_id);
    norm_g<<<(NG * 32 + 255) / 256, 256>>>(outC);
}